// round 2
// baseline (speedup 1.0000x reference)
#include <cuda_runtime.h>
#include <math.h>

// Problem constants
#define NRES 320
#define CCH  128
#define NH   4
#define DD   32
#define HD   128            // NH*DD
#define M_TOT (NRES*NRES)   // 102400
#define BIG_NEG (-1e9f)

// ---------------- scratch (device globals; no allocation allowed) ----------------
__device__ float g_x[M_TOT * CCH];        // layernormed act   [b,q,c]
__device__ float g_q[M_TOT * HD];         // [b,h,s,d]
__device__ float g_k[M_TOT * HD];         // [b,h,s,d]
__device__ float g_v[M_TOT * HD];         // [b,h,s,d]
__device__ float g_gate[M_TOT * HD];      // [b,q,f]
__device__ float g_wa[M_TOT * HD];        // [b,q,f]
__device__ float g_bias[NH * M_TOT];      // [h,q,k]

__device__ __forceinline__ float warpReduceSum(float v) {
    #pragma unroll
    for (int o = 16; o; o >>= 1) v += __shfl_xor_sync(0xffffffffu, v, o);
    return v;
}
__device__ __forceinline__ float warpReduceMax(float v) {
    #pragma unroll
    for (int o = 16; o; o >>= 1) v = fmaxf(v, __shfl_xor_sync(0xffffffffu, v, o));
    return v;
}

// ---------------- kernel 1: LayerNorm + pair-bias projection ----------------
// one warp per grid position; 8 warps per block
__global__ void ln_bias_kernel(const float* __restrict__ act,
                               const float* __restrict__ ln_scale,
                               const float* __restrict__ ln_bias,
                               const float* __restrict__ w_pb /* [C,H] */) {
    int warp = threadIdx.x >> 5, lane = threadIdx.x & 31;
    int pos = blockIdx.x * 8 + warp;
    if (pos >= M_TOT) return;
    size_t base = (size_t)pos * CCH + lane * 4;
    float4 x = *(const float4*)(act + base);

    float s = x.x + x.y + x.z + x.w;
    s = warpReduceSum(s);
    float mu = s * (1.0f / CCH);
    float dx = x.x - mu, dy = x.y - mu, dz = x.z - mu, dw = x.w - mu;
    float sq = dx*dx + dy*dy + dz*dz + dw*dw;
    sq = warpReduceSum(sq);
    float rstd = rsqrtf(sq * (1.0f / CCH) + 1e-5f);

    float4 sc = *(const float4*)(ln_scale + lane * 4);
    float4 bi = *(const float4*)(ln_bias + lane * 4);
    float4 y;
    y.x = dx * rstd * sc.x + bi.x;
    y.y = dy * rstd * sc.y + bi.y;
    y.z = dz * rstd * sc.z + bi.z;
    y.w = dw * rstd * sc.w + bi.w;
    *(float4*)(g_x + base) = y;

    // pair bias: bias[h] = sum_c y_c * w_pb[c][h]
    float4 acc = make_float4(0.f, 0.f, 0.f, 0.f);
    {
        float4 p0 = *(const float4*)(w_pb + (lane*4 + 0) * NH);
        float4 p1 = *(const float4*)(w_pb + (lane*4 + 1) * NH);
        float4 p2 = *(const float4*)(w_pb + (lane*4 + 2) * NH);
        float4 p3 = *(const float4*)(w_pb + (lane*4 + 3) * NH);
        acc.x = y.x*p0.x + y.y*p1.x + y.z*p2.x + y.w*p3.x;
        acc.y = y.x*p0.y + y.y*p1.y + y.z*p2.y + y.w*p3.y;
        acc.z = y.x*p0.z + y.y*p1.z + y.z*p2.z + y.w*p3.z;
        acc.w = y.x*p0.w + y.y*p1.w + y.z*p2.w + y.w*p3.w;
    }
    acc.x = warpReduceSum(acc.x);
    acc.y = warpReduceSum(acc.y);
    acc.z = warpReduceSum(acc.z);
    acc.w = warpReduceSum(acc.w);
    if (lane == 0) {
        g_bias[0 * M_TOT + pos] = acc.x;
        g_bias[1 * M_TOT + pos] = acc.y;
        g_bias[2 * M_TOT + pos] = acc.z;
        g_bias[3 * M_TOT + pos] = acc.w;
    }
}

// ---------------- kernel 2: fused QKV/gate projection GEMM ----------------
// X[102400,128] @ W[128,128] for 4 weight matrices (blockIdx.y selects)
// tile 128x128, 256 threads, 8x8 register micro-tile, BK=8
__global__ void __launch_bounds__(256, 2)
proj_kernel(const float* __restrict__ wq, const float* __restrict__ wk,
            const float* __restrict__ wv, const float* __restrict__ wg,
            const float* __restrict__ bg) {
    __shared__ float As[8 * 128];
    __shared__ float Bs[8 * 128];
    int mat = blockIdx.y;
    const float* W = (mat == 0) ? wq : (mat == 1) ? wk : (mat == 2) ? wv : wg;
    int m0 = blockIdx.x * 128;
    int t = threadIdx.x;
    int tx = t & 15, ty = t >> 4;
    int arow = t >> 1, acg = (t & 1) * 4;
    int brow = t >> 5, bcol = (t & 31) * 4;

    float acc[8][8];
    #pragma unroll
    for (int i = 0; i < 8; i++)
        #pragma unroll
        for (int j = 0; j < 8; j++) acc[i][j] = 0.f;

    for (int kt = 0; kt < CCH; kt += 8) {
        float4 av = *(const float4*)(g_x + (size_t)(m0 + arow) * CCH + kt + acg);
        As[(acg + 0) * 128 + arow] = av.x;
        As[(acg + 1) * 128 + arow] = av.y;
        As[(acg + 2) * 128 + arow] = av.z;
        As[(acg + 3) * 128 + arow] = av.w;
        *(float4*)(Bs + brow * 128 + bcol) =
            *(const float4*)(W + (size_t)(kt + brow) * HD + bcol);
        __syncthreads();
        #pragma unroll
        for (int k = 0; k < 8; k++) {
            float4 a0 = *(float4*)(As + k * 128 + ty * 8);
            float4 a1 = *(float4*)(As + k * 128 + ty * 8 + 4);
            float4 b0 = *(float4*)(Bs + k * 128 + tx * 8);
            float4 b1 = *(float4*)(Bs + k * 128 + tx * 8 + 4);
            float ra[8] = {a0.x, a0.y, a0.z, a0.w, a1.x, a1.y, a1.z, a1.w};
            float rb[8] = {b0.x, b0.y, b0.z, b0.w, b1.x, b1.y, b1.z, b1.w};
            #pragma unroll
            for (int i = 0; i < 8; i++)
                #pragma unroll
                for (int j = 0; j < 8; j++) acc[i][j] += ra[i] * rb[j];
        }
        __syncthreads();
    }

    const float qscale = 0.17677669529663687f; // 1/sqrt(32)
    #pragma unroll
    for (int i = 0; i < 8; i++) {
        int m = m0 + ty * 8 + i;
        int b = m / NRES, sp = m - b * NRES;
        size_t qkv_base = (size_t)b * (NH * NRES * DD) + (size_t)sp * DD;
        #pragma unroll
        for (int j = 0; j < 8; j++) {
            int f = tx * 8 + j;
            float v = acc[i][j];
            int h = f >> 5, d = f & 31;
            if (mat == 0)      g_q[qkv_base + (size_t)h * (NRES * DD) + d] = v * qscale;
            else if (mat == 1) g_k[qkv_base + (size_t)h * (NRES * DD) + d] = v;
            else if (mat == 2) g_v[qkv_base + (size_t)h * (NRES * DD) + d] = v;
            else {
                v = 1.0f / (1.0f + __expf(-(v + bg[f])));
                g_gate[(size_t)m * HD + f] = v;
            }
        }
    }
}

// ---------------- kernel 3: attention per (b,h) ----------------
// SMEM: K[320][33], V[320][33], Q[320][32], P[8][320], mask[320]
#define SM_K 0
#define SM_V 10560
#define SM_Q 21120
#define SM_P 31360
#define SM_M 33920
#define SM_TOTAL_F 34240

__global__ void __launch_bounds__(256, 1)
attn_kernel(const void* __restrict__ pmv) {
    extern __shared__ float sm[];
    float* Ksm = sm + SM_K;
    float* Vsm = sm + SM_V;
    float* Qsm = sm + SM_Q;
    float* Psm = sm + SM_P;
    float* Msm = sm + SM_M;

    int b = blockIdx.x >> 2, h = blockIdx.x & 3;
    size_t base = ((size_t)(b * NH + h)) * (NRES * DD);
    int t = threadIdx.x;

    for (int i = t; i < NRES * DD; i += 256) {
        int k = i >> 5, d = i & 31;
        Ksm[k * 33 + d] = g_k[base + i];
        Vsm[k * 33 + d] = g_v[base + i];
        Qsm[i] = g_q[base + i];
    }

    // pair_mask dtype sniff: bool is not a harness transport dtype, so the
    // buffer may be float32 (1.0f = 0x3F800000), packed bools (0x01010101),
    // or int32 (0x00000001). Decode per-element accordingly.
    {
        unsigned w0 = ((const unsigned*)pmv)[0];
        int mode = (w0 == 0x3F800000u) ? 0 : (w0 == 0x01010101u) ? 1 : 2;
        for (int i = t; i < NRES; i += 256) {
            size_t idx = (size_t)i * NRES + b;
            bool mv;
            if (mode == 0)      mv = ((const float*)pmv)[idx] != 0.0f;
            else if (mode == 1) mv = ((const unsigned char*)pmv)[idx] != 0;
            else                mv = ((const int*)pmv)[idx] != 0;
            Msm[i] = mv ? 1.0f : 0.0f;
        }
    }
    __syncthreads();

    int w = t >> 5, lane = t & 31;
    const float* biasbase = g_bias + (size_t)h * M_TOT;
    float* pr = Psm + w * NRES;

    for (int q = w; q < NRES; q += 8) {
        const float* Qv = Qsm + q * DD;
        float lg[10];
        #pragma unroll
        for (int kk = 0; kk < 10; kk++) lg[kk] = 0.f;
        #pragma unroll 8
        for (int d = 0; d < DD; d++) {
            float qd = Qv[d];
            #pragma unroll
            for (int kk = 0; kk < 10; kk++)
                lg[kk] += qd * Ksm[(lane + kk * 32) * 33 + d];
        }
        const float* brow = biasbase + (size_t)q * NRES;
        float mx = -3.0e38f;
        #pragma unroll
        for (int kk = 0; kk < 10; kk++) {
            int k = lane + kk * 32;
            float v = (Msm[k] != 0.f) ? (lg[kk] + __ldg(brow + k)) : BIG_NEG;
            lg[kk] = v;
            mx = fmaxf(mx, v);
        }
        mx = warpReduceMax(mx);
        float s = 0.f;
        #pragma unroll
        for (int kk = 0; kk < 10; kk++) {
            float e = __expf(lg[kk] - mx);
            lg[kk] = e;
            s += e;
        }
        s = warpReduceSum(s);
        float inv = 1.0f / s;
        #pragma unroll
        for (int kk = 0; kk < 10; kk++) pr[lane + kk * 32] = lg[kk] * inv;
        __syncwarp();

        float acc = 0.f;
        #pragma unroll 8
        for (int k = 0; k < NRES; k++)
            acc += pr[k] * Vsm[k * 33 + lane];
        g_wa[((size_t)b * NRES + q) * HD + h * DD + lane] = acc;
        __syncwarp();   // protect Psm (WAR across lanes for next q)
    }
}

// ---------------- kernel 4: output projection (gate fused into A-load) ----------------
__global__ void __launch_bounds__(256, 2)
out_kernel(const float* __restrict__ wo, const float* __restrict__ bo,
           float* __restrict__ out) {
    __shared__ float As[8 * 128];
    __shared__ float Bs[8 * 128];
    int m0 = blockIdx.x * 128;
    int t = threadIdx.x;
    int tx = t & 15, ty = t >> 4;
    int arow = t >> 1, acg = (t & 1) * 4;
    int brow = t >> 5, bcol = (t & 31) * 4;

    float acc[8][8];
    #pragma unroll
    for (int i = 0; i < 8; i++)
        #pragma unroll
        for (int j = 0; j < 8; j++) acc[i][j] = 0.f;

    for (int kt = 0; kt < HD; kt += 8) {
        size_t aoff = (size_t)(m0 + arow) * HD + kt + acg;
        float4 av = *(const float4*)(g_wa + aoff);
        float4 gv = *(const float4*)(g_gate + aoff);
        As[(acg + 0) * 128 + arow] = av.x * gv.x;
        As[(acg + 1) * 128 + arow] = av.y * gv.y;
        As[(acg + 2) * 128 + arow] = av.z * gv.z;
        As[(acg + 3) * 128 + arow] = av.w * gv.w;
        *(float4*)(Bs + brow * 128 + bcol) =
            *(const float4*)(wo + (size_t)(kt + brow) * CCH + bcol);
        __syncthreads();
        #pragma unroll
        for (int k = 0; k < 8; k++) {
            float4 a0 = *(float4*)(As + k * 128 + ty * 8);
            float4 a1 = *(float4*)(As + k * 128 + ty * 8 + 4);
            float4 b0 = *(float4*)(Bs + k * 128 + tx * 8);
            float4 b1 = *(float4*)(Bs + k * 128 + tx * 8 + 4);
            float ra[8] = {a0.x, a0.y, a0.z, a0.w, a1.x, a1.y, a1.z, a1.w};
            float rb[8] = {b0.x, b0.y, b0.z, b0.w, b1.x, b1.y, b1.z, b1.w};
            #pragma unroll
            for (int i = 0; i < 8; i++)
                #pragma unroll
                for (int j = 0; j < 8; j++) acc[i][j] += ra[i] * rb[j];
        }
        __syncthreads();
    }
    #pragma unroll
    for (int i = 0; i < 8; i++) {
        int m = m0 + ty * 8 + i;
        #pragma unroll
        for (int j = 0; j < 8; j++) {
            int c = tx * 8 + j;
            out[(size_t)m * CCH + c] = acc[i][j] + bo[c];
        }
    }
}

// ---------------- host ----------------
extern "C" void kernel_launch(void* const* d_in, const int* in_sizes, int n_in,
                              void* d_out, int out_size) {
    const float* act      = (const float*)d_in[0];
    const void*  pm       = d_in[1];
    const float* ln_scale = (const float*)d_in[2];
    const float* ln_bias  = (const float*)d_in[3];
    const float* w_pb     = (const float*)d_in[4];
    const float* w_q      = (const float*)d_in[5];
    const float* w_k      = (const float*)d_in[6];
    const float* w_v      = (const float*)d_in[7];
    const float* w_gate   = (const float*)d_in[8];
    const float* b_gate   = (const float*)d_in[9];
    const float* w_out    = (const float*)d_in[10];
    const float* b_out    = (const float*)d_in[11];
    float* out = (float*)d_out;

    ln_bias_kernel<<<M_TOT / 8, 256>>>(act, ln_scale, ln_bias, w_pb);
    proj_kernel<<<dim3(M_TOT / 128, 4), 256>>>(w_q, w_k, w_v, w_gate, b_gate);

    size_t attn_smem = (size_t)SM_TOTAL_F * sizeof(float); // 136,960 B
    cudaFuncSetAttribute(attn_kernel, cudaFuncAttributeMaxDynamicSharedMemorySize,
                         (int)attn_smem);
    attn_kernel<<<NRES * NH, 256, attn_smem>>>(pm);

    out_kernel<<<M_TOT / 128, 256>>>(w_out, b_out, out);
}

// round 5
// speedup vs baseline: 1.1130x; 1.1130x over previous
#include <cuda_runtime.h>
#include <cuda_bf16.h>
#include <math.h>
#include <stdint.h>

// Problem constants
#define NRES 320
#define CCH  128
#define NH   4
#define DD   32
#define HD   128            // NH*DD
#define M_TOT (NRES*NRES)   // 102400
#define BIG_NEG (-1e9f)
#define APAD 136            // smem row stride (bf16 elements), conflict-free
#define QSCALE 0.17677669529663687f  // 1/sqrt(32)

// ---------------- scratch (device globals; no allocation allowed) ----------------
__device__ __nv_bfloat16 g_xh[M_TOT * CCH];    // layernormed act, bf16 hi
__device__ __nv_bfloat16 g_xl[M_TOT * CCH];    // bf16 residual lo
__device__ __nv_bfloat16 g_wbh[5 * CCH * CCH]; // transposed split weights [mat][n][k]
__device__ __nv_bfloat16 g_wbl[5 * CCH * CCH];
__device__ float g_q[M_TOT * HD];         // [m][f]  f = h*32+d   (pre-scaled)
__device__ float g_k[M_TOT * HD];         // [m][f]
__device__ float g_v[M_TOT * HD];         // [m][f]
__device__ float g_gate[M_TOT * HD];      // [m][f]
__device__ float g_wa[M_TOT * HD];        // [m][f]
__device__ float g_bias[NH * M_TOT];      // [h,q,k]

__device__ __forceinline__ float warpReduceSum(float v) {
    #pragma unroll
    for (int o = 16; o; o >>= 1) v += __shfl_xor_sync(0xffffffffu, v, o);
    return v;
}
__device__ __forceinline__ float warpReduceMax(float v) {
    #pragma unroll
    for (int o = 16; o; o >>= 1) v = fmaxf(v, __shfl_xor_sync(0xffffffffu, v, o));
    return v;
}
__device__ __forceinline__ unsigned pack_bf2(__nv_bfloat16 a, __nv_bfloat16 b) {
    __nv_bfloat162 t = __halves2bfloat162(a, b);
    return *reinterpret_cast<unsigned*>(&t);
}

// warp-level bf16 mma (base PTX ISA, compiles on compute_103)
#define MMA_BF16(c, a, b0, b1) \
    asm volatile("mma.sync.aligned.m16n8k16.row.col.f32.bf16.bf16.f32 " \
        "{%0,%1,%2,%3}, {%4,%5,%6,%7}, {%8,%9}, {%0,%1,%2,%3};" \
        : "+f"((c)[0]), "+f"((c)[1]), "+f"((c)[2]), "+f"((c)[3]) \
        : "r"((a)[0]), "r"((a)[1]), "r"((a)[2]), "r"((a)[3]), "r"(b0), "r"(b1))

// ---------------- kernel 1: LayerNorm + pair-bias + split-bf16 emit ----------------
__global__ void ln_bias_kernel(const float* __restrict__ act,
                               const float* __restrict__ ln_scale,
                               const float* __restrict__ ln_bias,
                               const float* __restrict__ w_pb) {
    int warp = threadIdx.x >> 5, lane = threadIdx.x & 31;
    int pos = blockIdx.x * 8 + warp;
    if (pos >= M_TOT) return;
    size_t base = (size_t)pos * CCH + lane * 4;
    float4 x = *(const float4*)(act + base);

    float s = warpReduceSum(x.x + x.y + x.z + x.w);
    float mu = s * (1.0f / CCH);
    float dx = x.x - mu, dy = x.y - mu, dz = x.z - mu, dw = x.w - mu;
    float sq = warpReduceSum(dx*dx + dy*dy + dz*dz + dw*dw);
    float rstd = rsqrtf(sq * (1.0f / CCH) + 1e-5f);

    float4 sc = *(const float4*)(ln_scale + lane * 4);
    float4 bi = *(const float4*)(ln_bias + lane * 4);
    float4 y;
    y.x = dx * rstd * sc.x + bi.x;
    y.y = dy * rstd * sc.y + bi.y;
    y.z = dz * rstd * sc.z + bi.z;
    y.w = dw * rstd * sc.w + bi.w;

    __nv_bfloat16 hx = __float2bfloat16(y.x), hy = __float2bfloat16(y.y);
    __nv_bfloat16 hz = __float2bfloat16(y.z), hw = __float2bfloat16(y.w);
    __nv_bfloat16 lx = __float2bfloat16(y.x - __bfloat162float(hx));
    __nv_bfloat16 ly = __float2bfloat16(y.y - __bfloat162float(hy));
    __nv_bfloat16 lz = __float2bfloat16(y.z - __bfloat162float(hz));
    __nv_bfloat16 lw = __float2bfloat16(y.w - __bfloat162float(hw));
    uint2 hv, lv;
    hv.x = pack_bf2(hx, hy); hv.y = pack_bf2(hz, hw);
    lv.x = pack_bf2(lx, ly); lv.y = pack_bf2(lz, lw);
    *(uint2*)(g_xh + base) = hv;
    *(uint2*)(g_xl + base) = lv;

    float4 acc = make_float4(0.f, 0.f, 0.f, 0.f);
    {
        float4 p0 = *(const float4*)(w_pb + (lane*4 + 0) * NH);
        float4 p1 = *(const float4*)(w_pb + (lane*4 + 1) * NH);
        float4 p2 = *(const float4*)(w_pb + (lane*4 + 2) * NH);
        float4 p3 = *(const float4*)(w_pb + (lane*4 + 3) * NH);
        acc.x = y.x*p0.x + y.y*p1.x + y.z*p2.x + y.w*p3.x;
        acc.y = y.x*p0.y + y.y*p1.y + y.z*p2.y + y.w*p3.y;
        acc.z = y.x*p0.z + y.y*p1.z + y.z*p2.z + y.w*p3.z;
        acc.w = y.x*p0.w + y.y*p1.w + y.z*p2.w + y.w*p3.w;
    }
    acc.x = warpReduceSum(acc.x);
    acc.y = warpReduceSum(acc.y);
    acc.z = warpReduceSum(acc.z);
    acc.w = warpReduceSum(acc.w);
    if (lane == 0) {
        g_bias[0 * M_TOT + pos] = acc.x;
        g_bias[1 * M_TOT + pos] = acc.y;
        g_bias[2 * M_TOT + pos] = acc.z;
        g_bias[3 * M_TOT + pos] = acc.w;
    }
}

// ---------------- kernel 1b: weight transpose + split (5 matrices, 128x128) ----------------
__global__ void conv_w_kernel(const float* __restrict__ wq, const float* __restrict__ wk,
                              const float* __restrict__ wv, const float* __restrict__ wg,
                              const float* __restrict__ wo) {
    int mat = blockIdx.x;
    const float* W = (mat == 0) ? wq : (mat == 1) ? wk : (mat == 2) ? wv
                   : (mat == 3) ? wg : wo;
    int n = threadIdx.x;  // output col -> B row
    size_t dst = (size_t)mat * (CCH * CCH) + (size_t)n * CCH;
    for (int k = 0; k < CCH; k++) {
        float w = W[(size_t)k * CCH + n];   // B[n][k] = W[k][n] (col-major KxN)
        __nv_bfloat16 h = __float2bfloat16(w);
        __nv_bfloat16 l = __float2bfloat16(w - __bfloat162float(h));
        g_wbh[dst + k] = h;
        g_wbl[dst + k] = l;
    }
}

// ---------------- shared mma tile compute ----------------
// A [128][APAD] row-major (m,k), B [128][APAD] = col-major KxN ([n][k]).
// 8 warps: warp_m = wid&3 (32 rows), warp_n = wid>>2 (64 cols).
// Split-precision: C += Ah*Bh + Ah*Bl + Al*Bh.
__device__ __forceinline__ void mma_tile128(const __nv_bfloat16* __restrict__ Ah,
                                            const __nv_bfloat16* __restrict__ Al,
                                            const __nv_bfloat16* __restrict__ Bh,
                                            const __nv_bfloat16* __restrict__ Bl,
                                            int wid, int lane, float c[2][8][4]) {
    int warp_m = wid & 3, warp_n = wid >> 2;
    int g = lane >> 2, t4 = lane & 3;
    #pragma unroll
    for (int ks = 0; ks < 8; ks++) {
        int k0 = ks * 16 + t4 * 2;
        uint32_t ah[2][4], al[2][4];
        #pragma unroll
        for (int mf = 0; mf < 2; mf++) {
            const __nv_bfloat16* pa = Ah + (warp_m*32 + mf*16 + g) * APAD;
            const __nv_bfloat16* pl = Al + (warp_m*32 + mf*16 + g) * APAD;
            ah[mf][0] = *(const uint32_t*)(pa + k0);
            ah[mf][1] = *(const uint32_t*)(pa + 8*APAD + k0);
            ah[mf][2] = *(const uint32_t*)(pa + k0 + 8);
            ah[mf][3] = *(const uint32_t*)(pa + 8*APAD + k0 + 8);
            al[mf][0] = *(const uint32_t*)(pl + k0);
            al[mf][1] = *(const uint32_t*)(pl + 8*APAD + k0);
            al[mf][2] = *(const uint32_t*)(pl + k0 + 8);
            al[mf][3] = *(const uint32_t*)(pl + 8*APAD + k0 + 8);
        }
        #pragma unroll
        for (int nf = 0; nf < 8; nf++) {
            const __nv_bfloat16* pb = Bh + (warp_n*64 + nf*8 + g) * APAD;
            const __nv_bfloat16* pq = Bl + (warp_n*64 + nf*8 + g) * APAD;
            uint32_t bh0 = *(const uint32_t*)(pb + k0);
            uint32_t bh1 = *(const uint32_t*)(pb + k0 + 8);
            uint32_t bl0 = *(const uint32_t*)(pq + k0);
            uint32_t bl1 = *(const uint32_t*)(pq + k0 + 8);
            #pragma unroll
            for (int mf = 0; mf < 2; mf++) {
                MMA_BF16(c[mf][nf], ah[mf], bh0, bh1);
                MMA_BF16(c[mf][nf], ah[mf], bl0, bl1);
                MMA_BF16(c[mf][nf], al[mf], bh0, bh1);
            }
        }
    }
}

// smem element offsets (bf16)
#define SME_AH 0
#define SME_AL 17408
#define SME_BH 34816
#define SME_BL 52224
#define SME_TOT 69632
#define MMA_SMEM_BYTES (SME_TOT * 2 + 512)

// ---------------- kernel 2: QKV/gate projection GEMM (HMMA, split bf16) ----------------
__global__ void __launch_bounds__(256, 1)
proj_mma_kernel(const float* __restrict__ bg) {
    extern __shared__ __nv_bfloat16 sm[];
    __nv_bfloat16* Ah = sm + SME_AH;
    __nv_bfloat16* Al = sm + SME_AL;
    __nv_bfloat16* Bh = sm + SME_BH;
    __nv_bfloat16* Bl = sm + SME_BL;
    float* bgs = (float*)(sm + SME_TOT);

    int t = threadIdx.x, wid = t >> 5, lane = t & 31;
    int mat = blockIdx.y;
    int row = t >> 1, half = t & 1;

    if (t < 128) bgs[t] = bg[t];
    // load B (weights) once
    {
        const uint4* sH = (const uint4*)(g_wbh + ((size_t)mat * CCH + row) * CCH + half * 64);
        const uint4* sL = (const uint4*)(g_wbl + ((size_t)mat * CCH + row) * CCH + half * 64);
        uint4* dH = (uint4*)(Bh + row * APAD + half * 64);
        uint4* dL = (uint4*)(Bl + row * APAD + half * 64);
        #pragma unroll
        for (int c = 0; c < 8; c++) { dH[c] = sH[c]; dL[c] = sL[c]; }
    }

    float* dst = (mat == 0) ? g_q : (mat == 1) ? g_k : (mat == 2) ? g_v : g_gate;
    int warp_m = wid & 3, warp_n = wid >> 2;
    int g = lane >> 2, t4 = lane & 3;

    for (int it = 0; it < 4; it++) {
        __syncthreads();   // guards B on first iter, A/compute overlap after
        int m0 = (blockIdx.x * 4 + it) * 128;
        {
            const uint4* aH = (const uint4*)(g_xh + (size_t)(m0 + row) * CCH + half * 64);
            const uint4* aL = (const uint4*)(g_xl + (size_t)(m0 + row) * CCH + half * 64);
            uint4* dH = (uint4*)(Ah + row * APAD + half * 64);
            uint4* dL = (uint4*)(Al + row * APAD + half * 64);
            #pragma unroll
            for (int c = 0; c < 8; c++) { dH[c] = aH[c]; dL[c] = aL[c]; }
        }
        __syncthreads();

        float c[2][8][4];
        #pragma unroll
        for (int mf = 0; mf < 2; mf++)
            #pragma unroll
            for (int nf = 0; nf < 8; nf++)
                #pragma unroll
                for (int j = 0; j < 4; j++) c[mf][nf][j] = 0.f;

        mma_tile128(Ah, Al, Bh, Bl, wid, lane, c);

        #pragma unroll
        for (int mf = 0; mf < 2; mf++) {
            int r = m0 + warp_m * 32 + mf * 16 + g;
            #pragma unroll
            for (int nf = 0; nf < 8; nf++) {
                int cc = warp_n * 64 + nf * 8 + t4 * 2;
                float v0 = c[mf][nf][0], v1 = c[mf][nf][1];
                float v2 = c[mf][nf][2], v3 = c[mf][nf][3];
                if (mat == 0) { v0 *= QSCALE; v1 *= QSCALE; v2 *= QSCALE; v3 *= QSCALE; }
                else if (mat == 3) {
                    float b0 = bgs[cc], b1 = bgs[cc + 1];
                    v0 = 1.0f / (1.0f + __expf(-(v0 + b0)));
                    v1 = 1.0f / (1.0f + __expf(-(v1 + b1)));
                    v2 = 1.0f / (1.0f + __expf(-(v2 + b0)));
                    v3 = 1.0f / (1.0f + __expf(-(v3 + b1)));
                }
                *(float2*)(dst + (size_t)r * HD + cc) = make_float2(v0, v1);
                *(float2*)(dst + (size_t)(r + 8) * HD + cc) = make_float2(v2, v3);
            }
        }
    }
}

// ---------------- kernel 3: attention per (b,h) (scalar fp32, [m][f] layout) ----------------
#define SM_K 0
#define SM_V 10560
#define SM_Q 21120
#define SM_P 31360
#define SM_M 33920
#define SM_TOTAL_F 34240

__global__ void __launch_bounds__(256, 1)
attn_kernel(const void* __restrict__ pmv) {
    extern __shared__ float smf[];
    float* Ksm = smf + SM_K;
    float* Vsm = smf + SM_V;
    float* Qsm = smf + SM_Q;
    float* Psm = smf + SM_P;
    float* Msm = smf + SM_M;

    int b = blockIdx.x >> 2, h = blockIdx.x & 3;
    int t = threadIdx.x;
    size_t rowbase = (size_t)b * NRES * HD + (size_t)h * DD;

    for (int i = t; i < NRES * DD; i += 256) {
        int k = i >> 5, d = i & 31;
        size_t src = rowbase + (size_t)k * HD + d;
        Ksm[k * 33 + d] = g_k[src];
        Vsm[k * 33 + d] = g_v[src];
        Qsm[i] = g_q[src];
    }
    {
        unsigned w0 = ((const unsigned*)pmv)[0];
        int mode = (w0 == 0x3F800000u) ? 0 : (w0 == 0x01010101u) ? 1 : 2;
        for (int i = t; i < NRES; i += 256) {
            size_t idx = (size_t)i * NRES + b;
            bool mv;
            if (mode == 0)      mv = ((const float*)pmv)[idx] != 0.0f;
            else if (mode == 1) mv = ((const unsigned char*)pmv)[idx] != 0;
            else                mv = ((const int*)pmv)[idx] != 0;
            Msm[i] = mv ? 1.0f : 0.0f;
        }
    }
    __syncthreads();

    int w = t >> 5, lane = t & 31;
    const float* biasbase = g_bias + (size_t)h * M_TOT;
    float* pr = Psm + w * NRES;

    for (int q = w; q < NRES; q += 8) {
        const float* Qv = Qsm + q * DD;
        float lg[10];
        #pragma unroll
        for (int kk = 0; kk < 10; kk++) lg[kk] = 0.f;
        #pragma unroll 8
        for (int d = 0; d < DD; d++) {
            float qd = Qv[d];
            #pragma unroll
            for (int kk = 0; kk < 10; kk++)
                lg[kk] += qd * Ksm[(lane + kk * 32) * 33 + d];
        }
        const float* brow = biasbase + (size_t)q * NRES;
        float mx = -3.0e38f;
        #pragma unroll
        for (int kk = 0; kk < 10; kk++) {
            int k = lane + kk * 32;
            float v = (Msm[k] != 0.f) ? (lg[kk] + __ldg(brow + k)) : BIG_NEG;
            lg[kk] = v;
            mx = fmaxf(mx, v);
        }
        mx = warpReduceMax(mx);
        float s = 0.f;
        #pragma unroll
        for (int kk = 0; kk < 10; kk++) {
            float e = __expf(lg[kk] - mx);
            lg[kk] = e;
            s += e;
        }
        s = warpReduceSum(s);
        float inv = 1.0f / s;
        #pragma unroll
        for (int kk = 0; kk < 10; kk++) pr[lane + kk * 32] = lg[kk] * inv;
        __syncwarp();

        float acc = 0.f;
        #pragma unroll 8
        for (int k = 0; k < NRES; k++)
            acc += pr[k] * Vsm[k * 33 + lane];
        g_wa[((size_t)b * NRES + q) * HD + h * DD + lane] = acc;
        __syncwarp();
    }
}

// ---------------- kernel 4: output projection (HMMA, gate fused, split bf16) ----------------
__global__ void __launch_bounds__(256, 1)
out_mma_kernel(const float* __restrict__ bo, float* __restrict__ out) {
    extern __shared__ __nv_bfloat16 sm[];
    __nv_bfloat16* Ah = sm + SME_AH;
    __nv_bfloat16* Al = sm + SME_AL;
    __nv_bfloat16* Bh = sm + SME_BH;
    __nv_bfloat16* Bl = sm + SME_BL;
    float* bos = (float*)(sm + SME_TOT);

    int t = threadIdx.x, wid = t >> 5, lane = t & 31;
    int row = t >> 1, half = t & 1;
    if (t < 128) bos[t] = bo[t];

    {
        const uint4* sH = (const uint4*)(g_wbh + ((size_t)4 * CCH + row) * CCH + half * 64);
        const uint4* sL = (const uint4*)(g_wbl + ((size_t)4 * CCH + row) * CCH + half * 64);
        uint4* dH = (uint4*)(Bh + row * APAD + half * 64);
        uint4* dL = (uint4*)(Bl + row * APAD + half * 64);
        #pragma unroll
        for (int c = 0; c < 8; c++) { dH[c] = sH[c]; dL[c] = sL[c]; }
    }

    int warp_m = wid & 3, warp_n = wid >> 2;
    int g = lane >> 2, t4 = lane & 3;

    for (int it = 0; it < 4; it++) {
        __syncthreads();
        int m0 = (blockIdx.x * 4 + it) * 128;
        // A = wa * gate -> split bf16 into smem (64 floats per thread)
        {
            const float4* wa4 = (const float4*)(g_wa   + (size_t)(m0 + row) * HD + half * 64);
            const float4* gt4 = (const float4*)(g_gate + (size_t)(m0 + row) * HD + half * 64);
            uint2* dH = (uint2*)(Ah + row * APAD + half * 64);
            uint2* dL = (uint2*)(Al + row * APAD + half * 64);
            #pragma unroll
            for (int c = 0; c < 16; c++) {
                float4 a = wa4[c], q = gt4[c];
                float p0 = a.x * q.x, p1 = a.y * q.y, p2 = a.z * q.z, p3 = a.w * q.w;
                __nv_bfloat16 h0 = __float2bfloat16(p0), h1 = __float2bfloat16(p1);
                __nv_bfloat16 h2 = __float2bfloat16(p2), h3 = __float2bfloat16(p3);
                __nv_bfloat16 l0 = __float2bfloat16(p0 - __bfloat162float(h0));
                __nv_bfloat16 l1 = __float2bfloat16(p1 - __bfloat162float(h1));
                __nv_bfloat16 l2 = __float2bfloat16(p2 - __bfloat162float(h2));
                __nv_bfloat16 l3 = __float2bfloat16(p3 - __bfloat162float(h3));
                dH[c] = make_uint2(pack_bf2(h0, h1), pack_bf2(h2, h3));
                dL[c] = make_uint2(pack_bf2(l0, l1), pack_bf2(l2, l3));
            }
        }
        __syncthreads();

        float c[2][8][4];
        #pragma unroll
        for (int mf = 0; mf < 2; mf++)
            #pragma unroll
            for (int nf = 0; nf < 8; nf++)
                #pragma unroll
                for (int j = 0; j < 4; j++) c[mf][nf][j] = 0.f;

        mma_tile128(Ah, Al, Bh, Bl, wid, lane, c);

        #pragma unroll
        for (int mf = 0; mf < 2; mf++) {
            int r = m0 + warp_m * 32 + mf * 16 + g;
            #pragma unroll
            for (int nf = 0; nf < 8; nf++) {
                int cc = warp_n * 64 + nf * 8 + t4 * 2;
                float b0 = bos[cc], b1 = bos[cc + 1];
                *(float2*)(out + (size_t)r * CCH + cc) =
                    make_float2(c[mf][nf][0] + b0, c[mf][nf][1] + b1);
                *(float2*)(out + (size_t)(r + 8) * CCH + cc) =
                    make_float2(c[mf][nf][2] + b0, c[mf][nf][3] + b1);
            }
        }
    }
}

// ---------------- host ----------------
extern "C" void kernel_launch(void* const* d_in, const int* in_sizes, int n_in,
                              void* d_out, int out_size) {
    const float* act      = (const float*)d_in[0];
    const void*  pm       = d_in[1];
    const float* ln_scale = (const float*)d_in[2];
    const float* ln_bias  = (const float*)d_in[3];
    const float* w_pb     = (const float*)d_in[4];
    const float* w_q      = (const float*)d_in[5];
    const float* w_k      = (const float*)d_in[6];
    const float* w_v      = (const float*)d_in[7];
    const float* w_gate   = (const float*)d_in[8];
    const float* b_gate   = (const float*)d_in[9];
    const float* w_out    = (const float*)d_in[10];
    const float* b_out    = (const float*)d_in[11];
    float* out = (float*)d_out;

    conv_w_kernel<<<5, 128>>>(w_q, w_k, w_v, w_gate, w_out);
    ln_bias_kernel<<<M_TOT / 8, 256>>>(act, ln_scale, ln_bias, w_pb);

    cudaFuncSetAttribute(proj_mma_kernel, cudaFuncAttributeMaxDynamicSharedMemorySize,
                         MMA_SMEM_BYTES);
    proj_mma_kernel<<<dim3(200, 4), 256, MMA_SMEM_BYTES>>>(b_gate);

    size_t attn_smem = (size_t)SM_TOTAL_F * sizeof(float);
    cudaFuncSetAttribute(attn_kernel, cudaFuncAttributeMaxDynamicSharedMemorySize,
                         (int)attn_smem);
    attn_kernel<<<NRES * NH, 256, attn_smem>>>(pm);

    cudaFuncSetAttribute(out_mma_kernel, cudaFuncAttributeMaxDynamicSharedMemorySize,
                         MMA_SMEM_BYTES);
    out_mma_kernel<<<200, 256, MMA_SMEM_BYTES>>>(b_out, out);
}

// round 6
// speedup vs baseline: 2.4218x; 2.1759x over previous
#include <cuda_runtime.h>
#include <cuda_bf16.h>
#include <math.h>
#include <stdint.h>

// Problem constants
#define NRES 320
#define CCH  128
#define NH   4
#define DD   32
#define HD   128            // NH*DD
#define M_TOT (NRES*NRES)   // 102400
#define APAD 136            // GEMM smem row stride (bf16), conflict-free
#define QSCALE 0.17677669529663687f  // 1/sqrt(32)

// ---------------- scratch (device globals) ----------------
__device__ __nv_bfloat16 g_xh[M_TOT * CCH];
__device__ __nv_bfloat16 g_xl[M_TOT * CCH];
__device__ __nv_bfloat16 g_wbh[5 * CCH * CCH];  // [mat][n][k]
__device__ __nv_bfloat16 g_wbl[5 * CCH * CCH];
__device__ __nv_bfloat16 g_qh[M_TOT * HD];      // [m][f], pre-scaled
__device__ __nv_bfloat16 g_ql[M_TOT * HD];
__device__ __nv_bfloat16 g_kh[M_TOT * HD];
__device__ __nv_bfloat16 g_kl[M_TOT * HD];
__device__ __nv_bfloat16 g_vh[M_TOT * HD];
__device__ __nv_bfloat16 g_vl[M_TOT * HD];
__device__ float         g_gate[M_TOT * HD];
__device__ __nv_bfloat16 g_wah[M_TOT * HD];     // gated attn out, split bf16
__device__ __nv_bfloat16 g_wal[M_TOT * HD];
__device__ float         g_bias[NH * M_TOT];    // [h][q][k]

__device__ __forceinline__ float warpReduceSum(float v) {
    #pragma unroll
    for (int o = 16; o; o >>= 1) v += __shfl_xor_sync(0xffffffffu, v, o);
    return v;
}
__device__ __forceinline__ unsigned pack_bf2(__nv_bfloat16 a, __nv_bfloat16 b) {
    __nv_bfloat162 t = __halves2bfloat162(a, b);
    return *reinterpret_cast<unsigned*>(&t);
}
__device__ __forceinline__ void split2(float a, float b, uint32_t& hi, uint32_t& lo) {
    __nv_bfloat16 ha = __float2bfloat16(a), hb = __float2bfloat16(b);
    __nv_bfloat16 la = __float2bfloat16(a - __bfloat162float(ha));
    __nv_bfloat16 lb = __float2bfloat16(b - __bfloat162float(hb));
    hi = pack_bf2(ha, hb); lo = pack_bf2(la, lb);
}

#define MMA_BF16(c, a, b0, b1) \
    asm volatile("mma.sync.aligned.m16n8k16.row.col.f32.bf16.bf16.f32 " \
        "{%0,%1,%2,%3}, {%4,%5,%6,%7}, {%8,%9}, {%0,%1,%2,%3};" \
        : "+f"((c)[0]), "+f"((c)[1]), "+f"((c)[2]), "+f"((c)[3]) \
        : "r"((a)[0]), "r"((a)[1]), "r"((a)[2]), "r"((a)[3]), "r"(b0), "r"(b1))

// ---------------- kernel 1: LayerNorm + pair-bias + split-bf16 emit ----------------
__global__ void ln_bias_kernel(const float* __restrict__ act,
                               const float* __restrict__ ln_scale,
                               const float* __restrict__ ln_bias,
                               const float* __restrict__ w_pb) {
    int warp = threadIdx.x >> 5, lane = threadIdx.x & 31;
    int pos = blockIdx.x * 8 + warp;
    if (pos >= M_TOT) return;
    size_t base = (size_t)pos * CCH + lane * 4;
    float4 x = *(const float4*)(act + base);

    float s = warpReduceSum(x.x + x.y + x.z + x.w);
    float mu = s * (1.0f / CCH);
    float dx = x.x - mu, dy = x.y - mu, dz = x.z - mu, dw = x.w - mu;
    float sq = warpReduceSum(dx*dx + dy*dy + dz*dz + dw*dw);
    float rstd = rsqrtf(sq * (1.0f / CCH) + 1e-5f);

    float4 sc = *(const float4*)(ln_scale + lane * 4);
    float4 bi = *(const float4*)(ln_bias + lane * 4);
    float4 y;
    y.x = dx * rstd * sc.x + bi.x;
    y.y = dy * rstd * sc.y + bi.y;
    y.z = dz * rstd * sc.z + bi.z;
    y.w = dw * rstd * sc.w + bi.w;

    uint2 hv, lv;
    split2(y.x, y.y, hv.x, lv.x);
    split2(y.z, y.w, hv.y, lv.y);
    *(uint2*)(g_xh + base) = hv;
    *(uint2*)(g_xl + base) = lv;

    float4 acc = make_float4(0.f, 0.f, 0.f, 0.f);
    {
        float4 p0 = *(const float4*)(w_pb + (lane*4 + 0) * NH);
        float4 p1 = *(const float4*)(w_pb + (lane*4 + 1) * NH);
        float4 p2 = *(const float4*)(w_pb + (lane*4 + 2) * NH);
        float4 p3 = *(const float4*)(w_pb + (lane*4 + 3) * NH);
        acc.x = y.x*p0.x + y.y*p1.x + y.z*p2.x + y.w*p3.x;
        acc.y = y.x*p0.y + y.y*p1.y + y.z*p2.y + y.w*p3.y;
        acc.z = y.x*p0.z + y.y*p1.z + y.z*p2.z + y.w*p3.z;
        acc.w = y.x*p0.w + y.y*p1.w + y.z*p2.w + y.w*p3.w;
    }
    acc.x = warpReduceSum(acc.x);
    acc.y = warpReduceSum(acc.y);
    acc.z = warpReduceSum(acc.z);
    acc.w = warpReduceSum(acc.w);
    if (lane == 0) {
        g_bias[0 * M_TOT + pos] = acc.x;
        g_bias[1 * M_TOT + pos] = acc.y;
        g_bias[2 * M_TOT + pos] = acc.z;
        g_bias[3 * M_TOT + pos] = acc.w;
    }
}

// ---------------- kernel 1b: weight transpose + split ----------------
__global__ void conv_w_kernel(const float* __restrict__ wq, const float* __restrict__ wk,
                              const float* __restrict__ wv, const float* __restrict__ wg,
                              const float* __restrict__ wo) {
    int mat = blockIdx.x;
    const float* W = (mat == 0) ? wq : (mat == 1) ? wk : (mat == 2) ? wv
                   : (mat == 3) ? wg : wo;
    int n = threadIdx.x;
    size_t dst = (size_t)mat * (CCH * CCH) + (size_t)n * CCH;
    for (int k = 0; k < CCH; k++) {
        float w = W[(size_t)k * CCH + n];
        __nv_bfloat16 h = __float2bfloat16(w);
        g_wbh[dst + k] = h;
        g_wbl[dst + k] = __float2bfloat16(w - __bfloat162float(h));
    }
}

// ---------------- shared 128x128 mma tile ----------------
__device__ __forceinline__ void mma_tile128(const __nv_bfloat16* __restrict__ Ah,
                                            const __nv_bfloat16* __restrict__ Al,
                                            const __nv_bfloat16* __restrict__ Bh,
                                            const __nv_bfloat16* __restrict__ Bl,
                                            int wid, int lane, float c[2][8][4]) {
    int warp_m = wid & 3, warp_n = wid >> 2;
    int g = lane >> 2, t4 = lane & 3;
    #pragma unroll
    for (int ks = 0; ks < 8; ks++) {
        int k0 = ks * 16 + t4 * 2;
        uint32_t ah[2][4], al[2][4];
        #pragma unroll
        for (int mf = 0; mf < 2; mf++) {
            const __nv_bfloat16* pa = Ah + (warp_m*32 + mf*16 + g) * APAD;
            const __nv_bfloat16* pl = Al + (warp_m*32 + mf*16 + g) * APAD;
            ah[mf][0] = *(const uint32_t*)(pa + k0);
            ah[mf][1] = *(const uint32_t*)(pa + 8*APAD + k0);
            ah[mf][2] = *(const uint32_t*)(pa + k0 + 8);
            ah[mf][3] = *(const uint32_t*)(pa + 8*APAD + k0 + 8);
            al[mf][0] = *(const uint32_t*)(pl + k0);
            al[mf][1] = *(const uint32_t*)(pl + 8*APAD + k0);
            al[mf][2] = *(const uint32_t*)(pl + k0 + 8);
            al[mf][3] = *(const uint32_t*)(pl + 8*APAD + k0 + 8);
        }
        #pragma unroll
        for (int nf = 0; nf < 8; nf++) {
            const __nv_bfloat16* pb = Bh + (warp_n*64 + nf*8 + g) * APAD;
            const __nv_bfloat16* pq = Bl + (warp_n*64 + nf*8 + g) * APAD;
            uint32_t bh0 = *(const uint32_t*)(pb + k0);
            uint32_t bh1 = *(const uint32_t*)(pb + k0 + 8);
            uint32_t bl0 = *(const uint32_t*)(pq + k0);
            uint32_t bl1 = *(const uint32_t*)(pq + k0 + 8);
            #pragma unroll
            for (int mf = 0; mf < 2; mf++) {
                MMA_BF16(c[mf][nf], ah[mf], bh0, bh1);
                MMA_BF16(c[mf][nf], ah[mf], bl0, bl1);
                MMA_BF16(c[mf][nf], al[mf], bh0, bh1);
            }
        }
    }
}

#define SME_AH 0
#define SME_AL 17408
#define SME_BH 34816
#define SME_BL 52224
#define SME_TOT 69632
#define MMA_SMEM_BYTES (SME_TOT * 2 + 512)

// ---------------- kernel 2: QKV/gate projection ----------------
__global__ void __launch_bounds__(256, 1)
proj_mma_kernel(const float* __restrict__ bg) {
    extern __shared__ __nv_bfloat16 sm[];
    __nv_bfloat16* Ah = sm + SME_AH;
    __nv_bfloat16* Al = sm + SME_AL;
    __nv_bfloat16* Bh = sm + SME_BH;
    __nv_bfloat16* Bl = sm + SME_BL;
    float* bgs = (float*)(sm + SME_TOT);

    int t = threadIdx.x, wid = t >> 5, lane = t & 31;
    int mat = blockIdx.y;
    int row = t >> 1, half = t & 1;

    if (t < 128) bgs[t] = bg[t];
    {
        const uint4* sH = (const uint4*)(g_wbh + ((size_t)mat * CCH + row) * CCH + half * 64);
        const uint4* sL = (const uint4*)(g_wbl + ((size_t)mat * CCH + row) * CCH + half * 64);
        uint4* dH = (uint4*)(Bh + row * APAD + half * 64);
        uint4* dL = (uint4*)(Bl + row * APAD + half * 64);
        #pragma unroll
        for (int c = 0; c < 8; c++) { dH[c] = sH[c]; dL[c] = sL[c]; }
    }

    __nv_bfloat16* dsth = (mat == 0) ? g_qh : (mat == 1) ? g_kh : g_vh;
    __nv_bfloat16* dstl = (mat == 0) ? g_ql : (mat == 1) ? g_kl : g_vl;
    int warp_m = wid & 3, warp_n = wid >> 2;
    int g = lane >> 2, t4 = lane & 3;

    for (int it = 0; it < 4; it++) {
        __syncthreads();
        int m0 = (blockIdx.x * 4 + it) * 128;
        {
            const uint4* aH = (const uint4*)(g_xh + (size_t)(m0 + row) * CCH + half * 64);
            const uint4* aL = (const uint4*)(g_xl + (size_t)(m0 + row) * CCH + half * 64);
            uint4* dH = (uint4*)(Ah + row * APAD + half * 64);
            uint4* dL = (uint4*)(Al + row * APAD + half * 64);
            #pragma unroll
            for (int c = 0; c < 8; c++) { dH[c] = aH[c]; dL[c] = aL[c]; }
        }
        __syncthreads();

        float c[2][8][4];
        #pragma unroll
        for (int mf = 0; mf < 2; mf++)
            #pragma unroll
            for (int nf = 0; nf < 8; nf++)
                #pragma unroll
                for (int j = 0; j < 4; j++) c[mf][nf][j] = 0.f;

        mma_tile128(Ah, Al, Bh, Bl, wid, lane, c);

        #pragma unroll
        for (int mf = 0; mf < 2; mf++) {
            int r = m0 + warp_m * 32 + mf * 16 + g;
            #pragma unroll
            for (int nf = 0; nf < 8; nf++) {
                int cc = warp_n * 64 + nf * 8 + t4 * 2;
                float v0 = c[mf][nf][0], v1 = c[mf][nf][1];
                float v2 = c[mf][nf][2], v3 = c[mf][nf][3];
                if (mat == 3) {
                    float b0 = bgs[cc], b1 = bgs[cc + 1];
                    v0 = 1.0f / (1.0f + __expf(-(v0 + b0)));
                    v1 = 1.0f / (1.0f + __expf(-(v1 + b1)));
                    v2 = 1.0f / (1.0f + __expf(-(v2 + b0)));
                    v3 = 1.0f / (1.0f + __expf(-(v3 + b1)));
                    *(float2*)(g_gate + (size_t)r * HD + cc) = make_float2(v0, v1);
                    *(float2*)(g_gate + (size_t)(r + 8) * HD + cc) = make_float2(v2, v3);
                } else {
                    if (mat == 0) { v0 *= QSCALE; v1 *= QSCALE; v2 *= QSCALE; v3 *= QSCALE; }
                    uint32_t h0, l0, h1, l1;
                    split2(v0, v1, h0, l0);
                    split2(v2, v3, h1, l1);
                    *(uint32_t*)(dsth + (size_t)r * HD + cc) = h0;
                    *(uint32_t*)(dstl + (size_t)r * HD + cc) = l0;
                    *(uint32_t*)(dsth + (size_t)(r + 8) * HD + cc) = h1;
                    *(uint32_t*)(dstl + (size_t)(r + 8) * HD + cc) = l1;
                }
            }
        }
    }
}

// ---------------- kernel 3: attention per (b,h) on HMMA ----------------
// smem (bf16 elem offsets): KH 320x40, KL, VTH 32x328, VTL, QH 64x40, QL
#define AT_KH  0
#define AT_KL  12800
#define AT_VTH 25600
#define AT_VTL 36096
#define AT_QH  46592
#define AT_QL  49152
#define AT_FP  51712          // float region (byte 103424)
#define KPAD  40
#define VTPAD 328
#define OPAD  33
#define ATTN_SMEM (103424 + 2560 * 4)   // 113,664 B

__global__ void __launch_bounds__(256, 1)
attn_mma_kernel(const void* __restrict__ pmv) {
    extern __shared__ __nv_bfloat16 sb[];
    __nv_bfloat16* KH  = sb + AT_KH;
    __nv_bfloat16* KL  = sb + AT_KL;
    __nv_bfloat16* VTH = sb + AT_VTH;
    __nv_bfloat16* VTL = sb + AT_VTL;
    __nv_bfloat16* QH  = sb + AT_QH;
    __nv_bfloat16* QL  = sb + AT_QL;
    float* fp   = (float*)(sb + AT_FP);
    float* Msk  = fp;          // [320]
    float* Sums = fp + 320;    // [2][64]
    float* Osm  = fp + 448;    // [64][33]

    int b = blockIdx.x >> 2, h = blockIdx.x & 3;
    int t = threadIdx.x, wid = t >> 5, lane = t & 31;
    int g = lane >> 2, t4 = lane & 3;
    int warp_q = wid & 3, warp_k = wid >> 2;
    size_t mbase = (size_t)b * NRES * HD + (size_t)h * DD;

    // K + V(transposed) loads
    for (int i = t; i < 5120; i += 256) {
        int row = i >> 4, c2 = (i & 15) * 2;
        size_t src = mbase + (size_t)row * HD + c2;
        *(uint32_t*)(KH + row * KPAD + c2) = *(const uint32_t*)(g_kh + src);
        *(uint32_t*)(KL + row * KPAD + c2) = *(const uint32_t*)(g_kl + src);
        uint32_t vh = *(const uint32_t*)(g_vh + src);
        uint32_t vl = *(const uint32_t*)(g_vl + src);
        __nv_bfloat162 vh2 = *reinterpret_cast<__nv_bfloat162*>(&vh);
        __nv_bfloat162 vl2 = *reinterpret_cast<__nv_bfloat162*>(&vl);
        VTH[c2 * VTPAD + row] = vh2.x;
        VTH[(c2 + 1) * VTPAD + row] = vh2.y;
        VTL[c2 * VTPAD + row] = vl2.x;
        VTL[(c2 + 1) * VTPAD + row] = vl2.y;
    }
    {
        unsigned w0 = ((const unsigned*)pmv)[0];
        int mode = (w0 == 0x3F800000u) ? 0 : (w0 == 0x01010101u) ? 1 : 2;
        for (int i = t; i < NRES; i += 256) {
            size_t idx = (size_t)i * NRES + b;
            bool mv;
            if (mode == 0)      mv = ((const float*)pmv)[idx] != 0.0f;
            else if (mode == 1) mv = ((const unsigned char*)pmv)[idx] != 0;
            else                mv = ((const int*)pmv)[idx] != 0;
            Msk[i] = mv ? 1.0f : 0.0f;
        }
    }
    __syncthreads();

    for (int qt = 0; qt < 5; qt++) {
        int q0 = qt * 64;
        for (int i = t; i < 1024; i += 256) {
            int row = i >> 4, c2 = (i & 15) * 2;
            size_t src = mbase + (size_t)(q0 + row) * HD + c2;
            *(uint32_t*)(QH + row * KPAD + c2) = *(const uint32_t*)(g_qh + src);
            *(uint32_t*)(QL + row * KPAD + c2) = *(const uint32_t*)(g_ql + src);
        }
        __syncthreads();

        // ---- QK^T ----
        float c[20][4];
        #pragma unroll
        for (int nf = 0; nf < 20; nf++)
            #pragma unroll
            for (int j = 0; j < 4; j++) c[nf][j] = 0.f;

        uint32_t aH[2][4], aL[2][4];
        #pragma unroll
        for (int ks = 0; ks < 2; ks++) {
            const __nv_bfloat16* pa = QH + (warp_q*16 + g) * KPAD + ks*16 + 2*t4;
            const __nv_bfloat16* pl = QL + (warp_q*16 + g) * KPAD + ks*16 + 2*t4;
            aH[ks][0] = *(const uint32_t*)pa;
            aH[ks][1] = *(const uint32_t*)(pa + 8*KPAD);
            aH[ks][2] = *(const uint32_t*)(pa + 8);
            aH[ks][3] = *(const uint32_t*)(pa + 8*KPAD + 8);
            aL[ks][0] = *(const uint32_t*)pl;
            aL[ks][1] = *(const uint32_t*)(pl + 8*KPAD);
            aL[ks][2] = *(const uint32_t*)(pl + 8);
            aL[ks][3] = *(const uint32_t*)(pl + 8*KPAD + 8);
        }
        #pragma unroll
        for (int nf = 0; nf < 20; nf++) {
            int krow = warp_k*160 + nf*8 + g;
            #pragma unroll
            for (int ks = 0; ks < 2; ks++) {
                const __nv_bfloat16* pb = KH + krow * KPAD + ks*16 + 2*t4;
                const __nv_bfloat16* pq = KL + krow * KPAD + ks*16 + 2*t4;
                uint32_t bh0 = *(const uint32_t*)pb;
                uint32_t bh1 = *(const uint32_t*)(pb + 8);
                uint32_t bl0 = *(const uint32_t*)pq;
                uint32_t bl1 = *(const uint32_t*)(pq + 8);
                MMA_BF16(c[nf], aH[ks], bh0, bh1);
                MMA_BF16(c[nf], aH[ks], bl0, bl1);
                MMA_BF16(c[nf], aL[ks], bh0, bh1);
            }
        }

        // ---- bias + mask + exp + row sums (unnormalized softmax) ----
        int qr = q0 + warp_q*16 + g;
        const float* bp = g_bias + (size_t)h * M_TOT;
        float s0 = 0.f, s1 = 0.f;
        #pragma unroll
        for (int nf = 0; nf < 20; nf++) {
            int k = warp_k*160 + nf*8 + 2*t4;
            float2 b0 = *(const float2*)(bp + (size_t)qr * NRES + k);
            float2 b1 = *(const float2*)(bp + (size_t)(qr + 8) * NRES + k);
            float m0 = Msk[k], m1 = Msk[k + 1];
            c[nf][0] = __expf(fminf(c[nf][0] + b0.x, 60.f)) * m0;
            c[nf][1] = __expf(fminf(c[nf][1] + b0.y, 60.f)) * m1;
            c[nf][2] = __expf(fminf(c[nf][2] + b1.x, 60.f)) * m0;
            c[nf][3] = __expf(fminf(c[nf][3] + b1.y, 60.f)) * m1;
            s0 += c[nf][0] + c[nf][1];
            s1 += c[nf][2] + c[nf][3];
        }
        s0 += __shfl_xor_sync(0xffffffffu, s0, 1);
        s0 += __shfl_xor_sync(0xffffffffu, s0, 2);
        s1 += __shfl_xor_sync(0xffffffffu, s1, 1);
        s1 += __shfl_xor_sync(0xffffffffu, s1, 2);
        if (t4 == 0) {
            Sums[warp_k*64 + warp_q*16 + g]     = s0;
            Sums[warp_k*64 + warp_q*16 + g + 8] = s1;
        }

        // ---- P (registers, split) @ V ----
        float o[4][4];
        #pragma unroll
        for (int nf = 0; nf < 4; nf++)
            #pragma unroll
            for (int j = 0; j < 4; j++) o[nf][j] = 0.f;

        #pragma unroll
        for (int ks = 0; ks < 10; ks++) {
            uint32_t aPh[4], aPl[4];
            split2(c[2*ks][0],   c[2*ks][1],   aPh[0], aPl[0]);
            split2(c[2*ks][2],   c[2*ks][3],   aPh[1], aPl[1]);
            split2(c[2*ks+1][0], c[2*ks+1][1], aPh[2], aPl[2]);
            split2(c[2*ks+1][2], c[2*ks+1][3], aPh[3], aPl[3]);
            int k0 = warp_k*160 + ks*16 + 2*t4;
            #pragma unroll
            for (int nf = 0; nf < 4; nf++) {
                const __nv_bfloat16* pb = VTH + (nf*8 + g) * VTPAD + k0;
                const __nv_bfloat16* pq = VTL + (nf*8 + g) * VTPAD + k0;
                uint32_t bh0 = *(const uint32_t*)pb;
                uint32_t bh1 = *(const uint32_t*)(pb + 8);
                uint32_t bl0 = *(const uint32_t*)pq;
                uint32_t bl1 = *(const uint32_t*)(pq + 8);
                MMA_BF16(o[nf], aPh, bh0, bh1);
                MMA_BF16(o[nf], aPh, bl0, bl1);
                MMA_BF16(o[nf], aPl, bh0, bh1);
            }
        }

        // ---- combine warp_k halves ----
        int r0 = warp_q*16 + g;
        if (warp_k == 0) {
            #pragma unroll
            for (int nf = 0; nf < 4; nf++) {
                int cc = nf*8 + 2*t4;
                Osm[r0*OPAD + cc]       = o[nf][0];
                Osm[r0*OPAD + cc + 1]   = o[nf][1];
                Osm[(r0+8)*OPAD + cc]     = o[nf][2];
                Osm[(r0+8)*OPAD + cc + 1] = o[nf][3];
            }
        }
        __syncthreads();
        if (warp_k == 1) {
            #pragma unroll
            for (int nf = 0; nf < 4; nf++) {
                int cc = nf*8 + 2*t4;
                Osm[r0*OPAD + cc]       += o[nf][0];
                Osm[r0*OPAD + cc + 1]   += o[nf][1];
                Osm[(r0+8)*OPAD + cc]     += o[nf][2];
                Osm[(r0+8)*OPAD + cc + 1] += o[nf][3];
            }
        }
        __syncthreads();

        // ---- epilogue: normalize, gate, split-bf16 store ----
        {
            int row = t >> 2, cb = (t & 3) * 8;
            float den = Sums[row] + Sums[64 + row];
            float inv = (den > 0.f) ? 1.0f / den : 0.f;
            size_t m = (size_t)b * NRES + q0 + row;
            const float4* gp = (const float4*)(g_gate + m * HD + h * DD + cb);
            float4 gv0 = gp[0], gv1 = gp[1];
            float vv[8];
            vv[0] = Osm[row*OPAD + cb + 0] * inv * gv0.x;
            vv[1] = Osm[row*OPAD + cb + 1] * inv * gv0.y;
            vv[2] = Osm[row*OPAD + cb + 2] * inv * gv0.z;
            vv[3] = Osm[row*OPAD + cb + 3] * inv * gv0.w;
            vv[4] = Osm[row*OPAD + cb + 4] * inv * gv1.x;
            vv[5] = Osm[row*OPAD + cb + 5] * inv * gv1.y;
            vv[6] = Osm[row*OPAD + cb + 6] * inv * gv1.z;
            vv[7] = Osm[row*OPAD + cb + 7] * inv * gv1.w;
            size_t doff = m * HD + h * DD + cb;
            #pragma unroll
            for (int j = 0; j < 4; j++) {
                uint32_t hh, ll;
                split2(vv[2*j], vv[2*j+1], hh, ll);
                *(uint32_t*)(g_wah + doff + 2*j) = hh;
                *(uint32_t*)(g_wal + doff + 2*j) = ll;
            }
        }
        // next-tile Q-load __syncthreads provides the needed barrier
    }
}

// ---------------- kernel 4: output projection ----------------
__global__ void __launch_bounds__(256, 1)
out_mma_kernel(const float* __restrict__ bo, float* __restrict__ out) {
    extern __shared__ __nv_bfloat16 sm[];
    __nv_bfloat16* Ah = sm + SME_AH;
    __nv_bfloat16* Al = sm + SME_AL;
    __nv_bfloat16* Bh = sm + SME_BH;
    __nv_bfloat16* Bl = sm + SME_BL;
    float* bos = (float*)(sm + SME_TOT);

    int t = threadIdx.x, wid = t >> 5, lane = t & 31;
    int row = t >> 1, half = t & 1;
    if (t < 128) bos[t] = bo[t];

    {
        const uint4* sH = (const uint4*)(g_wbh + ((size_t)4 * CCH + row) * CCH + half * 64);
        const uint4* sL = (const uint4*)(g_wbl + ((size_t)4 * CCH + row) * CCH + half * 64);
        uint4* dH = (uint4*)(Bh + row * APAD + half * 64);
        uint4* dL = (uint4*)(Bl + row * APAD + half * 64);
        #pragma unroll
        for (int c = 0; c < 8; c++) { dH[c] = sH[c]; dL[c] = sL[c]; }
    }

    int warp_m = wid & 3, warp_n = wid >> 2;
    int g = lane >> 2, t4 = lane & 3;

    for (int it = 0; it < 4; it++) {
        __syncthreads();
        int m0 = (blockIdx.x * 4 + it) * 128;
        {
            const uint4* aH = (const uint4*)(g_wah + (size_t)(m0 + row) * HD + half * 64);
            const uint4* aL = (const uint4*)(g_wal + (size_t)(m0 + row) * HD + half * 64);
            uint4* dH = (uint4*)(Ah + row * APAD + half * 64);
            uint4* dL = (uint4*)(Al + row * APAD + half * 64);
            #pragma unroll
            for (int c = 0; c < 8; c++) { dH[c] = aH[c]; dL[c] = aL[c]; }
        }
        __syncthreads();

        float c[2][8][4];
        #pragma unroll
        for (int mf = 0; mf < 2; mf++)
            #pragma unroll
            for (int nf = 0; nf < 8; nf++)
                #pragma unroll
                for (int j = 0; j < 4; j++) c[mf][nf][j] = 0.f;

        mma_tile128(Ah, Al, Bh, Bl, wid, lane, c);

        #pragma unroll
        for (int mf = 0; mf < 2; mf++) {
            int r = m0 + warp_m * 32 + mf * 16 + g;
            #pragma unroll
            for (int nf = 0; nf < 8; nf++) {
                int cc = warp_n * 64 + nf * 8 + t4 * 2;
                float b0 = bos[cc], b1 = bos[cc + 1];
                *(float2*)(out + (size_t)r * CCH + cc) =
                    make_float2(c[mf][nf][0] + b0, c[mf][nf][1] + b1);
                *(float2*)(out + (size_t)(r + 8) * CCH + cc) =
                    make_float2(c[mf][nf][2] + b0, c[mf][nf][3] + b1);
            }
        }
    }
}

// ---------------- host ----------------
extern "C" void kernel_launch(void* const* d_in, const int* in_sizes, int n_in,
                              void* d_out, int out_size) {
    const float* act      = (const float*)d_in[0];
    const void*  pm       = d_in[1];
    const float* ln_scale = (const float*)d_in[2];
    const float* ln_bias  = (const float*)d_in[3];
    const float* w_pb     = (const float*)d_in[4];
    const float* w_q      = (const float*)d_in[5];
    const float* w_k      = (const float*)d_in[6];
    const float* w_v      = (const float*)d_in[7];
    const float* w_gate   = (const float*)d_in[8];
    const float* b_gate   = (const float*)d_in[9];
    const float* w_out    = (const float*)d_in[10];
    const float* b_out    = (const float*)d_in[11];
    float* out = (float*)d_out;

    conv_w_kernel<<<5, 128>>>(w_q, w_k, w_v, w_gate, w_out);
    ln_bias_kernel<<<M_TOT / 8, 256>>>(act, ln_scale, ln_bias, w_pb);

    cudaFuncSetAttribute(proj_mma_kernel, cudaFuncAttributeMaxDynamicSharedMemorySize,
                         MMA_SMEM_BYTES);
    proj_mma_kernel<<<dim3(200, 4), 256, MMA_SMEM_BYTES>>>(b_gate);

    cudaFuncSetAttribute(attn_mma_kernel, cudaFuncAttributeMaxDynamicSharedMemorySize,
                         ATTN_SMEM);
    attn_mma_kernel<<<NRES * NH, 256, ATTN_SMEM>>>(pm);

    cudaFuncSetAttribute(out_mma_kernel, cudaFuncAttributeMaxDynamicSharedMemorySize,
                         MMA_SMEM_BYTES);
    out_mma_kernel<<<200, 256, MMA_SMEM_BYTES>>>(b_out, out);
}

// round 8
// speedup vs baseline: 3.0311x; 1.2516x over previous
#include <cuda_runtime.h>
#include <cuda_bf16.h>
#include <math.h>
#include <stdint.h>

// Problem constants
#define NRES 320
#define CCH  128
#define NH   4
#define DD   32
#define HD   128            // NH*DD
#define M_TOT (NRES*NRES)   // 102400
#define APAD 136            // GEMM smem row stride (bf16), conflict-free
#define QSCALE 0.17677669529663687f  // 1/sqrt(32)

// ---------------- scratch (device globals) ----------------
__device__ __nv_bfloat16 g_xh[M_TOT * CCH];
__device__ __nv_bfloat16 g_xl[M_TOT * CCH];
__device__ __nv_bfloat16 g_wbh[5 * CCH * CCH];  // [mat][n][k]
__device__ __nv_bfloat16 g_wbl[5 * CCH * CCH];
__device__ __nv_bfloat16 g_qh[M_TOT * HD];      // [m][f], pre-scaled
__device__ __nv_bfloat16 g_ql[M_TOT * HD];
__device__ __nv_bfloat16 g_kh[M_TOT * HD];
__device__ __nv_bfloat16 g_kl[M_TOT * HD];
__device__ __nv_bfloat16 g_vh[M_TOT * HD];
__device__ __nv_bfloat16 g_vl[M_TOT * HD];
__device__ float         g_gate[M_TOT * HD];
__device__ __nv_bfloat16 g_wah[M_TOT * HD];     // gated attn out, split bf16
__device__ __nv_bfloat16 g_wal[M_TOT * HD];
__device__ float         g_bias[NH * M_TOT];    // [h][q][k]

__device__ __forceinline__ float warpReduceSum(float v) {
    #pragma unroll
    for (int o = 16; o; o >>= 1) v += __shfl_xor_sync(0xffffffffu, v, o);
    return v;
}
__device__ __forceinline__ unsigned pack_bf2(__nv_bfloat16 a, __nv_bfloat16 b) {
    __nv_bfloat162 t = __halves2bfloat162(a, b);
    return *reinterpret_cast<unsigned*>(&t);
}
__device__ __forceinline__ void split2(float a, float b, uint32_t& hi, uint32_t& lo) {
    __nv_bfloat16 ha = __float2bfloat16(a), hb = __float2bfloat16(b);
    __nv_bfloat16 la = __float2bfloat16(a - __bfloat162float(ha));
    __nv_bfloat16 lb = __float2bfloat16(b - __bfloat162float(hb));
    hi = pack_bf2(ha, hb); lo = pack_bf2(la, lb);
}

#define MMA_BF16(c, a, b0, b1) \
    asm volatile("mma.sync.aligned.m16n8k16.row.col.f32.bf16.bf16.f32 " \
        "{%0,%1,%2,%3}, {%4,%5,%6,%7}, {%8,%9}, {%0,%1,%2,%3};" \
        : "+f"((c)[0]), "+f"((c)[1]), "+f"((c)[2]), "+f"((c)[3]) \
        : "r"((a)[0]), "r"((a)[1]), "r"((a)[2]), "r"((a)[3]), "r"(b0), "r"(b1))

// ---------------- kernel 1: LayerNorm + pair-bias + split-bf16 emit ----------------
__global__ void ln_bias_kernel(const float* __restrict__ act,
                               const float* __restrict__ ln_scale,
                               const float* __restrict__ ln_bias,
                               const float* __restrict__ w_pb) {
    int warp = threadIdx.x >> 5, lane = threadIdx.x & 31;
    int pos = blockIdx.x * 8 + warp;
    if (pos >= M_TOT) return;
    size_t base = (size_t)pos * CCH + lane * 4;
    float4 x = *(const float4*)(act + base);

    float s = warpReduceSum(x.x + x.y + x.z + x.w);
    float mu = s * (1.0f / CCH);
    float dx = x.x - mu, dy = x.y - mu, dz = x.z - mu, dw = x.w - mu;
    float sq = warpReduceSum(dx*dx + dy*dy + dz*dz + dw*dw);
    float rstd = rsqrtf(sq * (1.0f / CCH) + 1e-5f);

    float4 sc = *(const float4*)(ln_scale + lane * 4);
    float4 bi = *(const float4*)(ln_bias + lane * 4);
    float4 y;
    y.x = dx * rstd * sc.x + bi.x;
    y.y = dy * rstd * sc.y + bi.y;
    y.z = dz * rstd * sc.z + bi.z;
    y.w = dw * rstd * sc.w + bi.w;

    uint2 hv, lv;
    split2(y.x, y.y, hv.x, lv.x);
    split2(y.z, y.w, hv.y, lv.y);
    *(uint2*)(g_xh + base) = hv;
    *(uint2*)(g_xl + base) = lv;

    float4 acc = make_float4(0.f, 0.f, 0.f, 0.f);
    {
        float4 p0 = *(const float4*)(w_pb + (lane*4 + 0) * NH);
        float4 p1 = *(const float4*)(w_pb + (lane*4 + 1) * NH);
        float4 p2 = *(const float4*)(w_pb + (lane*4 + 2) * NH);
        float4 p3 = *(const float4*)(w_pb + (lane*4 + 3) * NH);
        acc.x = y.x*p0.x + y.y*p1.x + y.z*p2.x + y.w*p3.x;
        acc.y = y.x*p0.y + y.y*p1.y + y.z*p2.y + y.w*p3.y;
        acc.z = y.x*p0.z + y.y*p1.z + y.z*p2.z + y.w*p3.z;
        acc.w = y.x*p0.w + y.y*p1.w + y.z*p2.w + y.w*p3.w;
    }
    acc.x = warpReduceSum(acc.x);
    acc.y = warpReduceSum(acc.y);
    acc.z = warpReduceSum(acc.z);
    acc.w = warpReduceSum(acc.w);
    if (lane == 0) {
        g_bias[0 * M_TOT + pos] = acc.x;
        g_bias[1 * M_TOT + pos] = acc.y;
        g_bias[2 * M_TOT + pos] = acc.z;
        g_bias[3 * M_TOT + pos] = acc.w;
    }
}

// ---------------- kernel 1b: weight transpose + split ----------------
__global__ void conv_w_kernel(const float* __restrict__ wq, const float* __restrict__ wk,
                              const float* __restrict__ wv, const float* __restrict__ wg,
                              const float* __restrict__ wo) {
    int mat = blockIdx.x;
    const float* W = (mat == 0) ? wq : (mat == 1) ? wk : (mat == 2) ? wv
                   : (mat == 3) ? wg : wo;
    int n = threadIdx.x;
    int k0 = blockIdx.y * 8;
    size_t dst = (size_t)mat * (CCH * CCH) + (size_t)n * CCH;
    #pragma unroll
    for (int kk = 0; kk < 8; kk++) {
        int k = k0 + kk;
        float w = W[(size_t)k * CCH + n];
        __nv_bfloat16 h = __float2bfloat16(w);
        g_wbh[dst + k] = h;
        g_wbl[dst + k] = __float2bfloat16(w - __bfloat162float(h));
    }
}

// ---------------- 64x128 mma tile (2 blocks/SM) ----------------
// A [64][APAD] (m,k); B [128][APAD] ([n][k] col-major KxN).
// 8 warps: warp_m = wid&1 (32 rows), warp_n = wid>>1 (32 cols).
__device__ __forceinline__ void mma_tile64(const __nv_bfloat16* __restrict__ Ah,
                                           const __nv_bfloat16* __restrict__ Al,
                                           const __nv_bfloat16* __restrict__ Bh,
                                           const __nv_bfloat16* __restrict__ Bl,
                                           int wid, int lane, float c[2][4][4]) {
    int warp_m = wid & 1, warp_n = wid >> 1;
    int g = lane >> 2, t4 = lane & 3;
    #pragma unroll
    for (int ks = 0; ks < 8; ks++) {
        int k0 = ks * 16 + t4 * 2;
        uint32_t ah[2][4], al[2][4];
        #pragma unroll
        for (int mf = 0; mf < 2; mf++) {
            const __nv_bfloat16* pa = Ah + (warp_m*32 + mf*16 + g) * APAD;
            const __nv_bfloat16* pl = Al + (warp_m*32 + mf*16 + g) * APAD;
            ah[mf][0] = *(const uint32_t*)(pa + k0);
            ah[mf][1] = *(const uint32_t*)(pa + 8*APAD + k0);
            ah[mf][2] = *(const uint32_t*)(pa + k0 + 8);
            ah[mf][3] = *(const uint32_t*)(pa + 8*APAD + k0 + 8);
            al[mf][0] = *(const uint32_t*)(pl + k0);
            al[mf][1] = *(const uint32_t*)(pl + 8*APAD + k0);
            al[mf][2] = *(const uint32_t*)(pl + k0 + 8);
            al[mf][3] = *(const uint32_t*)(pl + 8*APAD + k0 + 8);
        }
        #pragma unroll
        for (int nf = 0; nf < 4; nf++) {
            const __nv_bfloat16* pb = Bh + (warp_n*32 + nf*8 + g) * APAD;
            const __nv_bfloat16* pq = Bl + (warp_n*32 + nf*8 + g) * APAD;
            uint32_t bh0 = *(const uint32_t*)(pb + k0);
            uint32_t bh1 = *(const uint32_t*)(pb + k0 + 8);
            uint32_t bl0 = *(const uint32_t*)(pq + k0);
            uint32_t bl1 = *(const uint32_t*)(pq + k0 + 8);
            #pragma unroll
            for (int mf = 0; mf < 2; mf++) {
                MMA_BF16(c[mf][nf], ah[mf], bh0, bh1);
                MMA_BF16(c[mf][nf], ah[mf], bl0, bl1);
                MMA_BF16(c[mf][nf], al[mf], bh0, bh1);
            }
        }
    }
}

// smem element offsets (bf16)
#define SME_AH 0            // 64*136  = 8704
#define SME_AL 8704
#define SME_BH 17408        // 128*136 = 17408
#define SME_BL 34816
#define SME_TOT 52224
#define MMA_SMEM_BYTES (SME_TOT * 2 + 512)   // 104,960 B -> 2 blocks/SM

// ---------------- kernel 2: QKV/gate projection ----------------
__global__ void __launch_bounds__(256, 2)
proj_mma_kernel(const float* __restrict__ bg) {
    extern __shared__ __nv_bfloat16 sm[];
    __nv_bfloat16* Ah = sm + SME_AH;
    __nv_bfloat16* Al = sm + SME_AL;
    __nv_bfloat16* Bh = sm + SME_BH;
    __nv_bfloat16* Bl = sm + SME_BL;
    float* bgs = (float*)(sm + SME_TOT);

    int t = threadIdx.x, wid = t >> 5, lane = t & 31;
    int mat = blockIdx.y;

    if (t < 128) bgs[t] = bg[t];
    {   // B load: 128 rows, hi+lo
        int row = t >> 1, half = t & 1;
        const uint4* sH = (const uint4*)(g_wbh + ((size_t)mat * CCH + row) * CCH + half * 64);
        const uint4* sL = (const uint4*)(g_wbl + ((size_t)mat * CCH + row) * CCH + half * 64);
        uint4* dH = (uint4*)(Bh + row * APAD + half * 64);
        uint4* dL = (uint4*)(Bl + row * APAD + half * 64);
        #pragma unroll
        for (int c = 0; c < 8; c++) { dH[c] = sH[c]; dL[c] = sL[c]; }
    }

    __nv_bfloat16* dsth = (mat == 0) ? g_qh : (mat == 1) ? g_kh : g_vh;
    __nv_bfloat16* dstl = (mat == 0) ? g_ql : (mat == 1) ? g_kl : g_vl;
    int warp_m = wid & 1, warp_n = wid >> 1;
    int g = lane >> 2, t4 = lane & 3;
    int arow = t >> 2, aseg = t & 3;

    for (int it = 0; it < 4; it++) {
        __syncthreads();
        int m0 = (blockIdx.x * 4 + it) * 64;
        {   // A load: 64 rows
            const uint4* aH = (const uint4*)(g_xh + (size_t)(m0 + arow) * CCH + aseg * 32);
            const uint4* aL = (const uint4*)(g_xl + (size_t)(m0 + arow) * CCH + aseg * 32);
            uint4* dH = (uint4*)(Ah + arow * APAD + aseg * 32);
            uint4* dL = (uint4*)(Al + arow * APAD + aseg * 32);
            #pragma unroll
            for (int c = 0; c < 4; c++) { dH[c] = aH[c]; dL[c] = aL[c]; }
        }
        __syncthreads();

        float c[2][4][4];
        #pragma unroll
        for (int mf = 0; mf < 2; mf++)
            #pragma unroll
            for (int nf = 0; nf < 4; nf++)
                #pragma unroll
                for (int j = 0; j < 4; j++) c[mf][nf][j] = 0.f;

        mma_tile64(Ah, Al, Bh, Bl, wid, lane, c);

        #pragma unroll
        for (int mf = 0; mf < 2; mf++) {
            int r = m0 + warp_m * 32 + mf * 16 + g;
            #pragma unroll
            for (int nf = 0; nf < 4; nf++) {
                int cc = warp_n * 32 + nf * 8 + t4 * 2;
                float v0 = c[mf][nf][0], v1 = c[mf][nf][1];
                float v2 = c[mf][nf][2], v3 = c[mf][nf][3];
                if (mat == 3) {
                    float b0 = bgs[cc], b1 = bgs[cc + 1];
                    v0 = 1.0f / (1.0f + __expf(-(v0 + b0)));
                    v1 = 1.0f / (1.0f + __expf(-(v1 + b1)));
                    v2 = 1.0f / (1.0f + __expf(-(v2 + b0)));
                    v3 = 1.0f / (1.0f + __expf(-(v3 + b1)));
                    *(float2*)(g_gate + (size_t)r * HD + cc) = make_float2(v0, v1);
                    *(float2*)(g_gate + (size_t)(r + 8) * HD + cc) = make_float2(v2, v3);
                } else {
                    if (mat == 0) { v0 *= QSCALE; v1 *= QSCALE; v2 *= QSCALE; v3 *= QSCALE; }
                    uint32_t h0, l0, h1, l1;
                    split2(v0, v1, h0, l0);
                    split2(v2, v3, h1, l1);
                    *(uint32_t*)(dsth + (size_t)r * HD + cc) = h0;
                    *(uint32_t*)(dstl + (size_t)r * HD + cc) = l0;
                    *(uint32_t*)(dsth + (size_t)(r + 8) * HD + cc) = h1;
                    *(uint32_t*)(dstl + (size_t)(r + 8) * HD + cc) = l1;
                }
            }
        }
    }
}

// ---------------- kernel 3: attention per (b,h), 512 threads, 4-way K split ----------------
#define AT_KH  0
#define AT_KL  12800
#define AT_VTH 25600
#define AT_VTL 36096
#define AT_QH  46592
#define AT_QL  49152
#define AT_FP  51712          // float region at byte 103424
#define KPAD  40
#define VTPAD 328
#define OPAD  33
#define ATTN_SMEM (103424 + 2688 * 4)   // 114,176 B

__global__ void __launch_bounds__(512, 1)
attn_mma_kernel(const void* __restrict__ pmv) {
    extern __shared__ __nv_bfloat16 sb[];
    __nv_bfloat16* KH  = sb + AT_KH;
    __nv_bfloat16* KL  = sb + AT_KL;
    __nv_bfloat16* VTH = sb + AT_VTH;
    __nv_bfloat16* VTL = sb + AT_VTL;
    __nv_bfloat16* QH  = sb + AT_QH;
    __nv_bfloat16* QL  = sb + AT_QL;
    float* fp   = (float*)(sb + AT_FP);
    float* Msk  = fp;          // [320]
    float* Sums = fp + 320;    // [4][64]
    float* Osm  = fp + 576;    // [64][33]

    int b = blockIdx.x >> 2, h = blockIdx.x & 3;
    int t = threadIdx.x, wid = t >> 5, lane = t & 31;
    int g = lane >> 2, t4 = lane & 3;
    int warp_q = wid & 3, warp_k = wid >> 2;   // 4 x 4
    size_t mbase = (size_t)b * NRES * HD + (size_t)h * DD;

    for (int i = t; i < 5120; i += 512) {
        int row = i >> 4, c2 = (i & 15) * 2;
        size_t src = mbase + (size_t)row * HD + c2;
        *(uint32_t*)(KH + row * KPAD + c2) = *(const uint32_t*)(g_kh + src);
        *(uint32_t*)(KL + row * KPAD + c2) = *(const uint32_t*)(g_kl + src);
        uint32_t vh = *(const uint32_t*)(g_vh + src);
        uint32_t vl = *(const uint32_t*)(g_vl + src);
        __nv_bfloat162 vh2 = *reinterpret_cast<__nv_bfloat162*>(&vh);
        __nv_bfloat162 vl2 = *reinterpret_cast<__nv_bfloat162*>(&vl);
        VTH[c2 * VTPAD + row] = vh2.x;
        VTH[(c2 + 1) * VTPAD + row] = vh2.y;
        VTL[c2 * VTPAD + row] = vl2.x;
        VTL[(c2 + 1) * VTPAD + row] = vl2.y;
    }
    {
        unsigned w0 = ((const unsigned*)pmv)[0];
        int mode = (w0 == 0x3F800000u) ? 0 : (w0 == 0x01010101u) ? 1 : 2;
        for (int i = t; i < NRES; i += 512) {
            size_t idx = (size_t)i * NRES + b;
            bool mv;
            if (mode == 0)      mv = ((const float*)pmv)[idx] != 0.0f;
            else if (mode == 1) mv = ((const unsigned char*)pmv)[idx] != 0;
            else                mv = ((const int*)pmv)[idx] != 0;
            Msk[i] = mv ? 1.0f : 0.0f;
        }
    }
    __syncthreads();

    for (int qt = 0; qt < 5; qt++) {
        int q0 = qt * 64;
        for (int i = t; i < 1024; i += 512) {
            int row = i >> 4, c2 = (i & 15) * 2;
            size_t src = mbase + (size_t)(q0 + row) * HD + c2;
            *(uint32_t*)(QH + row * KPAD + c2) = *(const uint32_t*)(g_qh + src);
            *(uint32_t*)(QL + row * KPAD + c2) = *(const uint32_t*)(g_ql + src);
        }
        __syncthreads();

        // ---- QK^T over this warp's 80-key slice ----
        float c[10][4];
        #pragma unroll
        for (int nf = 0; nf < 10; nf++)
            #pragma unroll
            for (int j = 0; j < 4; j++) c[nf][j] = 0.f;

        uint32_t aH[2][4], aL[2][4];
        #pragma unroll
        for (int ks = 0; ks < 2; ks++) {
            const __nv_bfloat16* pa = QH + (warp_q*16 + g) * KPAD + ks*16 + 2*t4;
            const __nv_bfloat16* pl = QL + (warp_q*16 + g) * KPAD + ks*16 + 2*t4;
            aH[ks][0] = *(const uint32_t*)pa;
            aH[ks][1] = *(const uint32_t*)(pa + 8*KPAD);
            aH[ks][2] = *(const uint32_t*)(pa + 8);
            aH[ks][3] = *(const uint32_t*)(pa + 8*KPAD + 8);
            aL[ks][0] = *(const uint32_t*)pl;
            aL[ks][1] = *(const uint32_t*)(pl + 8*KPAD);
            aL[ks][2] = *(const uint32_t*)(pl + 8);
            aL[ks][3] = *(const uint32_t*)(pl + 8*KPAD + 8);
        }
        #pragma unroll
        for (int nf = 0; nf < 10; nf++) {
            int krow = warp_k*80 + nf*8 + g;
            #pragma unroll
            for (int ks = 0; ks < 2; ks++) {
                const __nv_bfloat16* pb = KH + krow * KPAD + ks*16 + 2*t4;
                const __nv_bfloat16* pq = KL + krow * KPAD + ks*16 + 2*t4;
                uint32_t bh0 = *(const uint32_t*)pb;
                uint32_t bh1 = *(const uint32_t*)(pb + 8);
                uint32_t bl0 = *(const uint32_t*)pq;
                uint32_t bl1 = *(const uint32_t*)(pq + 8);
                MMA_BF16(c[nf], aH[ks], bh0, bh1);
                MMA_BF16(c[nf], aH[ks], bl0, bl1);
                MMA_BF16(c[nf], aL[ks], bh0, bh1);
            }
        }

        // ---- bias + mask + exp + partial row sums ----
        int qr = q0 + warp_q*16 + g;
        const float* bp = g_bias + (size_t)h * M_TOT;
        float s0 = 0.f, s1 = 0.f;
        #pragma unroll
        for (int nf = 0; nf < 10; nf++) {
            int k = warp_k*80 + nf*8 + 2*t4;
            float2 b0 = *(const float2*)(bp + (size_t)qr * NRES + k);
            float2 b1 = *(const float2*)(bp + (size_t)(qr + 8) * NRES + k);
            float m0 = Msk[k], m1 = Msk[k + 1];
            c[nf][0] = __expf(fminf(c[nf][0] + b0.x, 60.f)) * m0;
            c[nf][1] = __expf(fminf(c[nf][1] + b0.y, 60.f)) * m1;
            c[nf][2] = __expf(fminf(c[nf][2] + b1.x, 60.f)) * m0;
            c[nf][3] = __expf(fminf(c[nf][3] + b1.y, 60.f)) * m1;
            s0 += c[nf][0] + c[nf][1];
            s1 += c[nf][2] + c[nf][3];
        }
        s0 += __shfl_xor_sync(0xffffffffu, s0, 1);
        s0 += __shfl_xor_sync(0xffffffffu, s0, 2);
        s1 += __shfl_xor_sync(0xffffffffu, s1, 1);
        s1 += __shfl_xor_sync(0xffffffffu, s1, 2);
        if (t4 == 0) {
            Sums[warp_k*64 + warp_q*16 + g]     = s0;
            Sums[warp_k*64 + warp_q*16 + g + 8] = s1;
        }

        // ---- P (registers, split) @ V over 80 keys ----
        float o[4][4];
        #pragma unroll
        for (int nf = 0; nf < 4; nf++)
            #pragma unroll
            for (int j = 0; j < 4; j++) o[nf][j] = 0.f;

        #pragma unroll
        for (int ks = 0; ks < 5; ks++) {
            uint32_t aPh[4], aPl[4];
            split2(c[2*ks][0],   c[2*ks][1],   aPh[0], aPl[0]);
            split2(c[2*ks][2],   c[2*ks][3],   aPh[1], aPl[1]);
            split2(c[2*ks+1][0], c[2*ks+1][1], aPh[2], aPl[2]);
            split2(c[2*ks+1][2], c[2*ks+1][3], aPh[3], aPl[3]);
            int k0 = warp_k*80 + ks*16 + 2*t4;
            #pragma unroll
            for (int nf = 0; nf < 4; nf++) {
                const __nv_bfloat16* pb = VTH + (nf*8 + g) * VTPAD + k0;
                const __nv_bfloat16* pq = VTL + (nf*8 + g) * VTPAD + k0;
                uint32_t bh0 = *(const uint32_t*)pb;
                uint32_t bh1 = *(const uint32_t*)(pb + 8);
                uint32_t bl0 = *(const uint32_t*)pq;
                uint32_t bl1 = *(const uint32_t*)(pq + 8);
                MMA_BF16(o[nf], aPh, bh0, bh1);
                MMA_BF16(o[nf], aPh, bl0, bl1);
                MMA_BF16(o[nf], aPl, bh0, bh1);
            }
        }

        // ---- staged combine across 4 warp_k groups ----
        int r0 = warp_q*16 + g;
        #pragma unroll
        for (int s = 0; s < 4; s++) {
            if (warp_k == s) {
                #pragma unroll
                for (int nf = 0; nf < 4; nf++) {
                    int cc = nf*8 + 2*t4;
                    if (s == 0) {
                        Osm[r0*OPAD + cc]         = o[nf][0];
                        Osm[r0*OPAD + cc + 1]     = o[nf][1];
                        Osm[(r0+8)*OPAD + cc]     = o[nf][2];
                        Osm[(r0+8)*OPAD + cc + 1] = o[nf][3];
                    } else {
                        Osm[r0*OPAD + cc]         += o[nf][0];
                        Osm[r0*OPAD + cc + 1]     += o[nf][1];
                        Osm[(r0+8)*OPAD + cc]     += o[nf][2];
                        Osm[(r0+8)*OPAD + cc + 1] += o[nf][3];
                    }
                }
            }
            __syncthreads();
        }

        // ---- epilogue: normalize, gate, split-bf16 store ----
        {
            int row = t >> 3, cb = (t & 7) * 4;
            float den = Sums[row] + Sums[64 + row] + Sums[128 + row] + Sums[192 + row];
            float inv = (den > 0.f) ? 1.0f / den : 0.f;
            size_t m = (size_t)b * NRES + q0 + row;
            float4 gv = *(const float4*)(g_gate + m * HD + h * DD + cb);
            float v0 = Osm[row*OPAD + cb + 0] * inv * gv.x;
            float v1 = Osm[row*OPAD + cb + 1] * inv * gv.y;
            float v2 = Osm[row*OPAD + cb + 2] * inv * gv.z;
            float v3 = Osm[row*OPAD + cb + 3] * inv * gv.w;
            size_t doff = m * HD + h * DD + cb;
            uint32_t hh, ll;
            split2(v0, v1, hh, ll);
            *(uint32_t*)(g_wah + doff) = hh;
            *(uint32_t*)(g_wal + doff) = ll;
            split2(v2, v3, hh, ll);
            *(uint32_t*)(g_wah + doff + 2) = hh;
            *(uint32_t*)(g_wal + doff + 2) = ll;
        }
        // next-tile Q-load __syncthreads separates epilogue reads from reuse
    }
}

// ---------------- kernel 4: output projection ----------------
__global__ void __launch_bounds__(256, 2)
out_mma_kernel(const float* __restrict__ bo, float* __restrict__ out) {
    extern __shared__ __nv_bfloat16 sm[];
    __nv_bfloat16* Ah = sm + SME_AH;
    __nv_bfloat16* Al = sm + SME_AL;
    __nv_bfloat16* Bh = sm + SME_BH;
    __nv_bfloat16* Bl = sm + SME_BL;
    float* bos = (float*)(sm + SME_TOT);

    int t = threadIdx.x, wid = t >> 5, lane = t & 31;
    if (t < 128) bos[t] = bo[t];
    {
        int row = t >> 1, half = t & 1;
        const uint4* sH = (const uint4*)(g_wbh + ((size_t)4 * CCH + row) * CCH + half * 64);
        const uint4* sL = (const uint4*)(g_wbl + ((size_t)4 * CCH + row) * CCH + half * 64);
        uint4* dH = (uint4*)(Bh + row * APAD + half * 64);
        uint4* dL = (uint4*)(Bl + row * APAD + half * 64);
        #pragma unroll
        for (int c = 0; c < 8; c++) { dH[c] = sH[c]; dL[c] = sL[c]; }
    }

    int warp_m = wid & 1, warp_n = wid >> 1;
    int g = lane >> 2, t4 = lane & 3;
    int arow = t >> 2, aseg = t & 3;

    for (int it = 0; it < 4; it++) {
        __syncthreads();
        int m0 = (blockIdx.x * 4 + it) * 64;
        {
            const uint4* aH = (const uint4*)(g_wah + (size_t)(m0 + arow) * HD + aseg * 32);
            const uint4* aL = (const uint4*)(g_wal + (size_t)(m0 + arow) * HD + aseg * 32);
            uint4* dH = (uint4*)(Ah + arow * APAD + aseg * 32);
            uint4* dL = (uint4*)(Al + arow * APAD + aseg * 32);
            #pragma unroll
            for (int c = 0; c < 4; c++) { dH[c] = aH[c]; dL[c] = aL[c]; }
        }
        __syncthreads();

        float c[2][4][4];
        #pragma unroll
        for (int mf = 0; mf < 2; mf++)
            #pragma unroll
            for (int nf = 0; nf < 4; nf++)
                #pragma unroll
                for (int j = 0; j < 4; j++) c[mf][nf][j] = 0.f;

        mma_tile64(Ah, Al, Bh, Bl, wid, lane, c);

        #pragma unroll
        for (int mf = 0; mf < 2; mf++) {
            int r = m0 + warp_m * 32 + mf * 16 + g;
            #pragma unroll
            for (int nf = 0; nf < 4; nf++) {
                int cc = warp_n * 32 + nf * 8 + t4 * 2;
                float b0 = bos[cc], b1 = bos[cc + 1];
                *(float2*)(out + (size_t)r * CCH + cc) =
                    make_float2(c[mf][nf][0] + b0, c[mf][nf][1] + b1);
                *(float2*)(out + (size_t)(r + 8) * CCH + cc) =
                    make_float2(c[mf][nf][2] + b0, c[mf][nf][3] + b1);
            }
        }
    }
}

// ---------------- host ----------------
extern "C" void kernel_launch(void* const* d_in, const int* in_sizes, int n_in,
                              void* d_out, int out_size) {
    const float* act      = (const float*)d_in[0];
    const void*  pm       = d_in[1];
    const float* ln_scale = (const float*)d_in[2];
    const float* ln_bias  = (const float*)d_in[3];
    const float* w_pb     = (const float*)d_in[4];
    const float* w_q      = (const float*)d_in[5];
    const float* w_k      = (const float*)d_in[6];
    const float* w_v      = (const float*)d_in[7];
    const float* w_gate   = (const float*)d_in[8];
    const float* b_gate   = (const float*)d_in[9];
    const float* w_out    = (const float*)d_in[10];
    const float* b_out    = (const float*)d_in[11];
    float* out = (float*)d_out;

    conv_w_kernel<<<dim3(5, 16), 128>>>(w_q, w_k, w_v, w_gate, w_out);
    ln_bias_kernel<<<M_TOT / 8, 256>>>(act, ln_scale, ln_bias, w_pb);

    cudaFuncSetAttribute(proj_mma_kernel, cudaFuncAttributeMaxDynamicSharedMemorySize,
                         MMA_SMEM_BYTES);
    proj_mma_kernel<<<dim3(400, 4), 256, MMA_SMEM_BYTES>>>(b_gate);

    cudaFuncSetAttribute(attn_mma_kernel, cudaFuncAttributeMaxDynamicSharedMemorySize,
                         ATTN_SMEM);
    attn_mma_kernel<<<NRES * NH, 512, ATTN_SMEM>>>(pm);

    cudaFuncSetAttribute(out_mma_kernel, cudaFuncAttributeMaxDynamicSharedMemorySize,
                         MMA_SMEM_BYTES);
    out_mma_kernel<<<400, 256, MMA_SMEM_BYTES>>>(b_out, out);
}

// round 12
// speedup vs baseline: 3.2275x; 1.0648x over previous
#include <cuda_runtime.h>
#include <cuda_bf16.h>
#include <math.h>
#include <stdint.h>

// Problem constants
#define NRES 320
#define CCH  128
#define NH   4
#define DD   32
#define HD   128            // NH*DD
#define M_TOT (NRES*NRES)   // 102400
#define APAD 136            // GEMM smem row stride (bf16), conflict-free
#define QSCALE 0.17677669529663687f  // 1/sqrt(32)

// ---------------- scratch (device globals) ----------------
__device__ __nv_bfloat16 g_xh[M_TOT * CCH];
__device__ __nv_bfloat16 g_xl[M_TOT * CCH];
__device__ __nv_bfloat16 g_wbh[5 * CCH * CCH];  // [mat][n][k]
__device__ __nv_bfloat16 g_wbl[5 * CCH * CCH];
__device__ __nv_bfloat16 g_qh[M_TOT * HD];      // [m][f], pre-scaled
__device__ __nv_bfloat16 g_ql[M_TOT * HD];
__device__ __nv_bfloat16 g_kh[M_TOT * HD];
__device__ __nv_bfloat16 g_kl[M_TOT * HD];
__device__ __nv_bfloat16 g_vh[M_TOT * HD];
__device__ __nv_bfloat16 g_vl[M_TOT * HD];
__device__ float         g_gate[M_TOT * HD];
__device__ __nv_bfloat16 g_wah[M_TOT * HD];     // gated attn out, split bf16
__device__ __nv_bfloat16 g_wal[M_TOT * HD];
__device__ float         g_bias[NH * M_TOT];    // [h][q][k]

__device__ __forceinline__ float warpReduceSum(float v) {
    #pragma unroll
    for (int o = 16; o; o >>= 1) v += __shfl_xor_sync(0xffffffffu, v, o);
    return v;
}
__device__ __forceinline__ unsigned pack_bf2(__nv_bfloat16 a, __nv_bfloat16 b) {
    __nv_bfloat162 t = __halves2bfloat162(a, b);
    return *reinterpret_cast<unsigned*>(&t);
}
__device__ __forceinline__ void split2(float a, float b, uint32_t& hi, uint32_t& lo) {
    __nv_bfloat16 ha = __float2bfloat16(a), hb = __float2bfloat16(b);
    __nv_bfloat16 la = __float2bfloat16(a - __bfloat162float(ha));
    __nv_bfloat16 lb = __float2bfloat16(b - __bfloat162float(hb));
    hi = pack_bf2(ha, hb); lo = pack_bf2(la, lb);
}

#define MMA_BF16(c, a, b0, b1) \
    asm volatile("mma.sync.aligned.m16n8k16.row.col.f32.bf16.bf16.f32 " \
        "{%0,%1,%2,%3}, {%4,%5,%6,%7}, {%8,%9}, {%0,%1,%2,%3};" \
        : "+f"((c)[0]), "+f"((c)[1]), "+f"((c)[2]), "+f"((c)[3]) \
        : "r"((a)[0]), "r"((a)[1]), "r"((a)[2]), "r"((a)[3]), "r"(b0), "r"(b1))

// ---------------- kernel 1: LayerNorm + pair-bias + split-bf16 emit ----------------
__global__ void ln_bias_kernel(const float* __restrict__ act,
                               const float* __restrict__ ln_scale,
                               const float* __restrict__ ln_bias,
                               const float* __restrict__ w_pb) {
    int warp = threadIdx.x >> 5, lane = threadIdx.x & 31;
    int pos = blockIdx.x * 8 + warp;
    if (pos >= M_TOT) return;
    size_t base = (size_t)pos * CCH + lane * 4;
    float4 x = *(const float4*)(act + base);

    float s = warpReduceSum(x.x + x.y + x.z + x.w);
    float mu = s * (1.0f / CCH);
    float dx = x.x - mu, dy = x.y - mu, dz = x.z - mu, dw = x.w - mu;
    float sq = warpReduceSum(dx*dx + dy*dy + dz*dz + dw*dw);
    float rstd = rsqrtf(sq * (1.0f / CCH) + 1e-5f);

    float4 sc = *(const float4*)(ln_scale + lane * 4);
    float4 bi = *(const float4*)(ln_bias + lane * 4);
    float4 y;
    y.x = dx * rstd * sc.x + bi.x;
    y.y = dy * rstd * sc.y + bi.y;
    y.z = dz * rstd * sc.z + bi.z;
    y.w = dw * rstd * sc.w + bi.w;

    uint2 hv, lv;
    split2(y.x, y.y, hv.x, lv.x);
    split2(y.z, y.w, hv.y, lv.y);
    *(uint2*)(g_xh + base) = hv;
    *(uint2*)(g_xl + base) = lv;

    float4 acc = make_float4(0.f, 0.f, 0.f, 0.f);
    {
        float4 p0 = *(const float4*)(w_pb + (lane*4 + 0) * NH);
        float4 p1 = *(const float4*)(w_pb + (lane*4 + 1) * NH);
        float4 p2 = *(const float4*)(w_pb + (lane*4 + 2) * NH);
        float4 p3 = *(const float4*)(w_pb + (lane*4 + 3) * NH);
        acc.x = y.x*p0.x + y.y*p1.x + y.z*p2.x + y.w*p3.x;
        acc.y = y.x*p0.y + y.y*p1.y + y.z*p2.y + y.w*p3.y;
        acc.z = y.x*p0.z + y.y*p1.z + y.z*p2.z + y.w*p3.z;
        acc.w = y.x*p0.w + y.y*p1.w + y.z*p2.w + y.w*p3.w;
    }
    acc.x = warpReduceSum(acc.x);
    acc.y = warpReduceSum(acc.y);
    acc.z = warpReduceSum(acc.z);
    acc.w = warpReduceSum(acc.w);
    if (lane == 0) {
        g_bias[0 * M_TOT + pos] = acc.x;
        g_bias[1 * M_TOT + pos] = acc.y;
        g_bias[2 * M_TOT + pos] = acc.z;
        g_bias[3 * M_TOT + pos] = acc.w;
    }
}

// ---------------- kernel 1b: weight transpose + split ----------------
__global__ void conv_w_kernel(const float* __restrict__ wq, const float* __restrict__ wk,
                              const float* __restrict__ wv, const float* __restrict__ wg,
                              const float* __restrict__ wo) {
    int mat = blockIdx.x;
    const float* W = (mat == 0) ? wq : (mat == 1) ? wk : (mat == 2) ? wv
                   : (mat == 3) ? wg : wo;
    int n = threadIdx.x;
    int k0 = blockIdx.y * 8;
    size_t dst = (size_t)mat * (CCH * CCH) + (size_t)n * CCH;
    #pragma unroll
    for (int kk = 0; kk < 8; kk++) {
        int k = k0 + kk;
        float w = W[(size_t)k * CCH + n];
        __nv_bfloat16 h = __float2bfloat16(w);
        g_wbh[dst + k] = h;
        g_wbl[dst + k] = __float2bfloat16(w - __bfloat162float(h));
    }
}

// ---------------- 64x128 mma tile ----------------
__device__ __forceinline__ void mma_tile64(const __nv_bfloat16* __restrict__ Ah,
                                           const __nv_bfloat16* __restrict__ Al,
                                           const __nv_bfloat16* __restrict__ Bh,
                                           const __nv_bfloat16* __restrict__ Bl,
                                           int wid, int lane, float c[2][4][4]) {
    int warp_m = wid & 1, warp_n = wid >> 1;
    int g = lane >> 2, t4 = lane & 3;
    #pragma unroll
    for (int ks = 0; ks < 8; ks++) {
        int k0 = ks * 16 + t4 * 2;
        uint32_t ah[2][4], al[2][4];
        #pragma unroll
        for (int mf = 0; mf < 2; mf++) {
            const __nv_bfloat16* pa = Ah + (warp_m*32 + mf*16 + g) * APAD;
            const __nv_bfloat16* pl = Al + (warp_m*32 + mf*16 + g) * APAD;
            ah[mf][0] = *(const uint32_t*)(pa + k0);
            ah[mf][1] = *(const uint32_t*)(pa + 8*APAD + k0);
            ah[mf][2] = *(const uint32_t*)(pa + k0 + 8);
            ah[mf][3] = *(const uint32_t*)(pa + 8*APAD + k0 + 8);
            al[mf][0] = *(const uint32_t*)(pl + k0);
            al[mf][1] = *(const uint32_t*)(pl + 8*APAD + k0);
            al[mf][2] = *(const uint32_t*)(pl + k0 + 8);
            al[mf][3] = *(const uint32_t*)(pl + 8*APAD + k0 + 8);
        }
        #pragma unroll
        for (int nf = 0; nf < 4; nf++) {
            const __nv_bfloat16* pb = Bh + (warp_n*32 + nf*8 + g) * APAD;
            const __nv_bfloat16* pq = Bl + (warp_n*32 + nf*8 + g) * APAD;
            uint32_t bh0 = *(const uint32_t*)(pb + k0);
            uint32_t bh1 = *(const uint32_t*)(pb + k0 + 8);
            uint32_t bl0 = *(const uint32_t*)(pq + k0);
            uint32_t bl1 = *(const uint32_t*)(pq + k0 + 8);
            #pragma unroll
            for (int mf = 0; mf < 2; mf++) {
                MMA_BF16(c[mf][nf], ah[mf], bh0, bh1);
                MMA_BF16(c[mf][nf], ah[mf], bl0, bl1);
                MMA_BF16(c[mf][nf], al[mf], bh0, bh1);
            }
        }
    }
}

#define SME_AH 0
#define SME_AL 8704
#define SME_BH 17408
#define SME_BL 34816
#define SME_TOT 52224
#define MMA_SMEM_BYTES (SME_TOT * 2 + 512)   // 104,960 B -> 2 blocks/SM

// ---------------- kernel 2: QKV/gate projection (A prefetch pipeline) ----------------
__global__ void __launch_bounds__(256, 2)
proj_mma_kernel(const float* __restrict__ bg) {
    extern __shared__ __nv_bfloat16 sm[];
    __nv_bfloat16* Ah = sm + SME_AH;
    __nv_bfloat16* Al = sm + SME_AL;
    __nv_bfloat16* Bh = sm + SME_BH;
    __nv_bfloat16* Bl = sm + SME_BL;
    float* bgs = (float*)(sm + SME_TOT);

    int t = threadIdx.x, wid = t >> 5, lane = t & 31;
    int mat = blockIdx.y;

    if (t < 128) bgs[t] = bg[t];
    {
        int row = t >> 1, half = t & 1;
        const uint4* sH = (const uint4*)(g_wbh + ((size_t)mat * CCH + row) * CCH + half * 64);
        const uint4* sL = (const uint4*)(g_wbl + ((size_t)mat * CCH + row) * CCH + half * 64);
        uint4* dH = (uint4*)(Bh + row * APAD + half * 64);
        uint4* dL = (uint4*)(Bl + row * APAD + half * 64);
        #pragma unroll
        for (int c = 0; c < 8; c++) { dH[c] = sH[c]; dL[c] = sL[c]; }
    }

    __nv_bfloat16* dsth = (mat == 0) ? g_qh : (mat == 1) ? g_kh : g_vh;
    __nv_bfloat16* dstl = (mat == 0) ? g_ql : (mat == 1) ? g_kl : g_vl;
    int warp_m = wid & 1, warp_n = wid >> 1;
    int g = lane >> 2, t4 = lane & 3;
    int arow = t >> 2, aseg = t & 3;

    // prefetch A tile 0
    uint4 pH[4], pL[4];
    {
        int m0 = blockIdx.x * 4 * 64;
        const uint4* aH = (const uint4*)(g_xh + (size_t)(m0 + arow) * CCH + aseg * 32);
        const uint4* aL = (const uint4*)(g_xl + (size_t)(m0 + arow) * CCH + aseg * 32);
        #pragma unroll
        for (int c = 0; c < 4; c++) { pH[c] = aH[c]; pL[c] = aL[c]; }
    }

    for (int it = 0; it < 4; it++) {
        __syncthreads();   // previous mma done reading A; B visible on it=0 via 2nd sync
        int m0 = (blockIdx.x * 4 + it) * 64;
        {
            uint4* dH = (uint4*)(Ah + arow * APAD + aseg * 32);
            uint4* dL = (uint4*)(Al + arow * APAD + aseg * 32);
            #pragma unroll
            for (int c = 0; c < 4; c++) { dH[c] = pH[c]; dL[c] = pL[c]; }
        }
        __syncthreads();
        if (it < 3) {   // issue next-tile loads; they fly during the mma phase
            int m1 = (blockIdx.x * 4 + it + 1) * 64;
            const uint4* aH = (const uint4*)(g_xh + (size_t)(m1 + arow) * CCH + aseg * 32);
            const uint4* aL = (const uint4*)(g_xl + (size_t)(m1 + arow) * CCH + aseg * 32);
            #pragma unroll
            for (int c = 0; c < 4; c++) { pH[c] = aH[c]; pL[c] = aL[c]; }
        }

        float c[2][4][4];
        #pragma unroll
        for (int mf = 0; mf < 2; mf++)
            #pragma unroll
            for (int nf = 0; nf < 4; nf++)
                #pragma unroll
                for (int j = 0; j < 4; j++) c[mf][nf][j] = 0.f;

        mma_tile64(Ah, Al, Bh, Bl, wid, lane, c);

        #pragma unroll
        for (int mf = 0; mf < 2; mf++) {
            int r = m0 + warp_m * 32 + mf * 16 + g;
            #pragma unroll
            for (int nf = 0; nf < 4; nf++) {
                int cc = warp_n * 32 + nf * 8 + t4 * 2;
                float v0 = c[mf][nf][0], v1 = c[mf][nf][1];
                float v2 = c[mf][nf][2], v3 = c[mf][nf][3];
                if (mat == 3) {
                    float b0 = bgs[cc], b1 = bgs[cc + 1];
                    v0 = 1.0f / (1.0f + __expf(-(v0 + b0)));
                    v1 = 1.0f / (1.0f + __expf(-(v1 + b1)));
                    v2 = 1.0f / (1.0f + __expf(-(v2 + b0)));
                    v3 = 1.0f / (1.0f + __expf(-(v3 + b1)));
                    *(float2*)(g_gate + (size_t)r * HD + cc) = make_float2(v0, v1);
                    *(float2*)(g_gate + (size_t)(r + 8) * HD + cc) = make_float2(v2, v3);
                } else {
                    if (mat == 0) { v0 *= QSCALE; v1 *= QSCALE; v2 *= QSCALE; v3 *= QSCALE; }
                    uint32_t h0, l0, h1, l1;
                    split2(v0, v1, h0, l0);
                    split2(v2, v3, h1, l1);
                    *(uint32_t*)(dsth + (size_t)r * HD + cc) = h0;
                    *(uint32_t*)(dstl + (size_t)r * HD + cc) = l0;
                    *(uint32_t*)(dsth + (size_t)(r + 8) * HD + cc) = h1;
                    *(uint32_t*)(dstl + (size_t)(r + 8) * HD + cc) = l1;
                }
            }
        }
    }
}

// ---------------- kernel 3: attention, 512 threads, parallel partial buffers ----------------
#define AT_KH  0
#define AT_KL  12800
#define AT_VTH 25600
#define AT_VTL 36096
#define AT_QH  46592
#define AT_QL  49152
#define AT_FP  51712          // float region at byte 103424
#define KPAD  40
#define VTPAD 328
#define OPAD  33
#define OSZ   (64 * OPAD)     // 2112 floats per partial buffer
#define ATTN_SMEM (103424 + (320 + 256 + 4 * OSZ) * 4)   // 139,520 B

__global__ void __launch_bounds__(512, 1)
attn_mma_kernel(const void* __restrict__ pmv) {
    extern __shared__ __nv_bfloat16 sb[];
    __nv_bfloat16* KH  = sb + AT_KH;
    __nv_bfloat16* KL  = sb + AT_KL;
    __nv_bfloat16* VTH = sb + AT_VTH;
    __nv_bfloat16* VTL = sb + AT_VTL;
    __nv_bfloat16* QH  = sb + AT_QH;
    __nv_bfloat16* QL  = sb + AT_QL;
    float* fp   = (float*)(sb + AT_FP);
    float* Msk  = fp;          // [320]
    float* Sums = fp + 320;    // [4][64]
    float* OsmP = fp + 576;    // [4][64][33]

    int b = blockIdx.x >> 2, h = blockIdx.x & 3;
    int t = threadIdx.x, wid = t >> 5, lane = t & 31;
    int g = lane >> 2, t4 = lane & 3;
    int warp_q = wid & 3, warp_k = wid >> 2;
    size_t mbase = (size_t)b * NRES * HD + (size_t)h * DD;

    for (int i = t; i < 5120; i += 512) {
        int row = i >> 4, c2 = (i & 15) * 2;
        size_t src = mbase + (size_t)row * HD + c2;
        *(uint32_t*)(KH + row * KPAD + c2) = *(const uint32_t*)(g_kh + src);
        *(uint32_t*)(KL + row * KPAD + c2) = *(const uint32_t*)(g_kl + src);
        uint32_t vh = *(const uint32_t*)(g_vh + src);
        uint32_t vl = *(const uint32_t*)(g_vl + src);
        __nv_bfloat162 vh2 = *reinterpret_cast<__nv_bfloat162*>(&vh);
        __nv_bfloat162 vl2 = *reinterpret_cast<__nv_bfloat162*>(&vl);
        VTH[c2 * VTPAD + row] = vh2.x;
        VTH[(c2 + 1) * VTPAD + row] = vh2.y;
        VTL[c2 * VTPAD + row] = vl2.x;
        VTL[(c2 + 1) * VTPAD + row] = vl2.y;
    }
    {
        unsigned w0 = ((const unsigned*)pmv)[0];
        int mode = (w0 == 0x3F800000u) ? 0 : (w0 == 0x01010101u) ? 1 : 2;
        for (int i = t; i < NRES; i += 512) {
            size_t idx = (size_t)i * NRES + b;
            bool mv;
            if (mode == 0)      mv = ((const float*)pmv)[idx] != 0.0f;
            else if (mode == 1) mv = ((const unsigned char*)pmv)[idx] != 0;
            else                mv = ((const int*)pmv)[idx] != 0;
            Msk[i] = mv ? 1.0f : 0.0f;
        }
    }
    __syncthreads();

    for (int qt = 0; qt < 5; qt++) {
        int q0 = qt * 64;
        for (int i = t; i < 1024; i += 512) {
            int row = i >> 4, c2 = (i & 15) * 2;
            size_t src = mbase + (size_t)(q0 + row) * HD + c2;
            *(uint32_t*)(QH + row * KPAD + c2) = *(const uint32_t*)(g_qh + src);
            *(uint32_t*)(QL + row * KPAD + c2) = *(const uint32_t*)(g_ql + src);
        }
        __syncthreads();   // Q ready; also: all prior-iter epilogue Osm reads done

        // ---- QK^T over this warp's 80-key slice ----
        float c[10][4];
        #pragma unroll
        for (int nf = 0; nf < 10; nf++)
            #pragma unroll
            for (int j = 0; j < 4; j++) c[nf][j] = 0.f;

        uint32_t aH[2][4], aL[2][4];
        #pragma unroll
        for (int ks = 0; ks < 2; ks++) {
            const __nv_bfloat16* pa = QH + (warp_q*16 + g) * KPAD + ks*16 + 2*t4;
            const __nv_bfloat16* pl = QL + (warp_q*16 + g) * KPAD + ks*16 + 2*t4;
            aH[ks][0] = *(const uint32_t*)pa;
            aH[ks][1] = *(const uint32_t*)(pa + 8*KPAD);
            aH[ks][2] = *(const uint32_t*)(pa + 8);
            aH[ks][3] = *(const uint32_t*)(pa + 8*KPAD + 8);
            aL[ks][0] = *(const uint32_t*)pl;
            aL[ks][1] = *(const uint32_t*)(pl + 8*KPAD);
            aL[ks][2] = *(const uint32_t*)(pl + 8);
            aL[ks][3] = *(const uint32_t*)(pl + 8*KPAD + 8);
        }
        #pragma unroll
        for (int nf = 0; nf < 10; nf++) {
            int krow = warp_k*80 + nf*8 + g;
            #pragma unroll
            for (int ks = 0; ks < 2; ks++) {
                const __nv_bfloat16* pb = KH + krow * KPAD + ks*16 + 2*t4;
                const __nv_bfloat16* pq = KL + krow * KPAD + ks*16 + 2*t4;
                uint32_t bh0 = *(const uint32_t*)pb;
                uint32_t bh1 = *(const uint32_t*)(pb + 8);
                uint32_t bl0 = *(const uint32_t*)pq;
                uint32_t bl1 = *(const uint32_t*)(pq + 8);
                MMA_BF16(c[nf], aH[ks], bh0, bh1);
                MMA_BF16(c[nf], aH[ks], bl0, bl1);
                MMA_BF16(c[nf], aL[ks], bh0, bh1);
            }
        }

        // ---- bias + mask + exp + partial row sums ----
        int qr = q0 + warp_q*16 + g;
        const float* bp = g_bias + (size_t)h * M_TOT;
        float s0 = 0.f, s1 = 0.f;
        #pragma unroll
        for (int nf = 0; nf < 10; nf++) {
            int k = warp_k*80 + nf*8 + 2*t4;
            float2 b0 = *(const float2*)(bp + (size_t)qr * NRES + k);
            float2 b1 = *(const float2*)(bp + (size_t)(qr + 8) * NRES + k);
            float m0 = Msk[k], m1 = Msk[k + 1];
            c[nf][0] = __expf(c[nf][0] + b0.x) * m0;
            c[nf][1] = __expf(c[nf][1] + b0.y) * m1;
            c[nf][2] = __expf(c[nf][2] + b1.x) * m0;
            c[nf][3] = __expf(c[nf][3] + b1.y) * m1;
            s0 += c[nf][0] + c[nf][1];
            s1 += c[nf][2] + c[nf][3];
        }
        s0 += __shfl_xor_sync(0xffffffffu, s0, 1);
        s0 += __shfl_xor_sync(0xffffffffu, s0, 2);
        s1 += __shfl_xor_sync(0xffffffffu, s1, 1);
        s1 += __shfl_xor_sync(0xffffffffu, s1, 2);
        if (t4 == 0) {
            Sums[warp_k*64 + warp_q*16 + g]     = s0;
            Sums[warp_k*64 + warp_q*16 + g + 8] = s1;
        }

        // ---- P (registers, split) @ V over 80 keys ----
        float o[4][4];
        #pragma unroll
        for (int nf = 0; nf < 4; nf++)
            #pragma unroll
            for (int j = 0; j < 4; j++) o[nf][j] = 0.f;

        #pragma unroll
        for (int ks = 0; ks < 5; ks++) {
            uint32_t aPh[4], aPl[4];
            split2(c[2*ks][0],   c[2*ks][1],   aPh[0], aPl[0]);
            split2(c[2*ks][2],   c[2*ks][3],   aPh[1], aPl[1]);
            split2(c[2*ks+1][0], c[2*ks+1][1], aPh[2], aPl[2]);
            split2(c[2*ks+1][2], c[2*ks+1][3], aPh[3], aPl[3]);
            int k0 = warp_k*80 + ks*16 + 2*t4;
            #pragma unroll
            for (int nf = 0; nf < 4; nf++) {
                const __nv_bfloat16* pb = VTH + (nf*8 + g) * VTPAD + k0;
                const __nv_bfloat16* pq = VTL + (nf*8 + g) * VTPAD + k0;
                uint32_t bh0 = *(const uint32_t*)pb;
                uint32_t bh1 = *(const uint32_t*)(pb + 8);
                uint32_t bl0 = *(const uint32_t*)pq;
                uint32_t bl1 = *(const uint32_t*)(pq + 8);
                MMA_BF16(o[nf], aPh, bh0, bh1);
                MMA_BF16(o[nf], aPh, bl0, bl1);
                MMA_BF16(o[nf], aPl, bh0, bh1);
            }
        }

        // ---- each warp_k group writes its OWN partial buffer (no staging) ----
        {
            float* myO = OsmP + warp_k * OSZ;
            int r0 = warp_q*16 + g;
            #pragma unroll
            for (int nf = 0; nf < 4; nf++) {
                int cc = nf*8 + 2*t4;
                myO[r0*OPAD + cc]         = o[nf][0];
                myO[r0*OPAD + cc + 1]     = o[nf][1];
                myO[(r0+8)*OPAD + cc]     = o[nf][2];
                myO[(r0+8)*OPAD + cc + 1] = o[nf][3];
            }
        }
        __syncthreads();

        // ---- epilogue: sum partials, normalize, gate, split-bf16 store ----
        {
            int row = t >> 3, cb = (t & 7) * 4;
            float den = Sums[row] + Sums[64 + row] + Sums[128 + row] + Sums[192 + row];
            float inv = (den > 0.f) ? 1.0f / den : 0.f;
            int ob = row * OPAD + cb;
            float v0 = OsmP[ob+0] + OsmP[OSZ+ob+0] + OsmP[2*OSZ+ob+0] + OsmP[3*OSZ+ob+0];
            float v1 = OsmP[ob+1] + OsmP[OSZ+ob+1] + OsmP[2*OSZ+ob+1] + OsmP[3*OSZ+ob+1];
            float v2 = OsmP[ob+2] + OsmP[OSZ+ob+2] + OsmP[2*OSZ+ob+2] + OsmP[3*OSZ+ob+2];
            float v3 = OsmP[ob+3] + OsmP[OSZ+ob+3] + OsmP[2*OSZ+ob+3] + OsmP[3*OSZ+ob+3];
            size_t m = (size_t)b * NRES + q0 + row;
            float4 gv = *(const float4*)(g_gate + m * HD + h * DD + cb);
            v0 *= inv * gv.x; v1 *= inv * gv.y; v2 *= inv * gv.z; v3 *= inv * gv.w;
            size_t doff = m * HD + h * DD + cb;
            uint32_t hh, ll;
            split2(v0, v1, hh, ll);
            *(uint32_t*)(g_wah + doff) = hh;
            *(uint32_t*)(g_wal + doff) = ll;
            split2(v2, v3, hh, ll);
            *(uint32_t*)(g_wah + doff + 2) = hh;
            *(uint32_t*)(g_wal + doff + 2) = ll;
        }
        // next-iter Q-load sync separates epilogue reads from next PV writes
    }
}

// ---------------- kernel 4: output projection (A prefetch pipeline) ----------------
__global__ void __launch_bounds__(256, 2)
out_mma_kernel(const float* __restrict__ bo, float* __restrict__ out) {
    extern __shared__ __nv_bfloat16 sm[];
    __nv_bfloat16* Ah = sm + SME_AH;
    __nv_bfloat16* Al = sm + SME_AL;
    __nv_bfloat16* Bh = sm + SME_BH;
    __nv_bfloat16* Bl = sm + SME_BL;
    float* bos = (float*)(sm + SME_TOT);

    int t = threadIdx.x, wid = t >> 5, lane = t & 31;
    if (t < 128) bos[t] = bo[t];
    {
        int row = t >> 1, half = t & 1;
        const uint4* sH = (const uint4*)(g_wbh + ((size_t)4 * CCH + row) * CCH + half * 64);
        const uint4* sL = (const uint4*)(g_wbl + ((size_t)4 * CCH + row) * CCH + half * 64);
        uint4* dH = (uint4*)(Bh + row * APAD + half * 64);
        uint4* dL = (uint4*)(Bl + row * APAD + half * 64);
        #pragma unroll
        for (int c = 0; c < 8; c++) { dH[c] = sH[c]; dL[c] = sL[c]; }
    }

    int warp_m = wid & 1, warp_n = wid >> 1;
    int g = lane >> 2, t4 = lane & 3;
    int arow = t >> 2, aseg = t & 3;

    uint4 pH[4], pL[4];
    {
        int m0 = blockIdx.x * 4 * 64;
        const uint4* aH = (const uint4*)(g_wah + (size_t)(m0 + arow) * HD + aseg * 32);
        const uint4* aL = (const uint4*)(g_wal + (size_t)(m0 + arow) * HD + aseg * 32);
        #pragma unroll
        for (int c = 0; c < 4; c++) { pH[c] = aH[c]; pL[c] = aL[c]; }
    }

    for (int it = 0; it < 4; it++) {
        __syncthreads();
        int m0 = (blockIdx.x * 4 + it) * 64;
        {
            uint4* dH = (uint4*)(Ah + arow * APAD + aseg * 32);
            uint4* dL = (uint4*)(Al + arow * APAD + aseg * 32);
            #pragma unroll
            for (int c = 0; c < 4; c++) { dH[c] = pH[c]; dL[c] = pL[c]; }
        }
        __syncthreads();
        if (it < 3) {
            int m1 = (blockIdx.x * 4 + it + 1) * 64;
            const uint4* aH = (const uint4*)(g_wah + (size_t)(m1 + arow) * HD + aseg * 32);
            const uint4* aL = (const uint4*)(g_wal + (size_t)(m1 + arow) * HD + aseg * 32);
            #pragma unroll
            for (int c = 0; c < 4; c++) { pH[c] = aH[c]; pL[c] = aL[c]; }
        }

        float c[2][4][4];
        #pragma unroll
        for (int mf = 0; mf < 2; mf++)
            #pragma unroll
            for (int nf = 0; nf < 4; nf++)
                #pragma unroll
                for (int j = 0; j < 4; j++) c[mf][nf][j] = 0.f;

        mma_tile64(Ah, Al, Bh, Bl, wid, lane, c);

        #pragma unroll
        for (int mf = 0; mf < 2; mf++) {
            int r = m0 + warp_m * 32 + mf * 16 + g;
            #pragma unroll
            for (int nf = 0; nf < 4; nf++) {
                int cc = warp_n * 32 + nf * 8 + t4 * 2;
                float b0 = bos[cc], b1 = bos[cc + 1];
                *(float2*)(out + (size_t)r * CCH + cc) =
                    make_float2(c[mf][nf][0] + b0, c[mf][nf][1] + b1);
                *(float2*)(out + (size_t)(r + 8) * CCH + cc) =
                    make_float2(c[mf][nf][2] + b0, c[mf][nf][3] + b1);
            }
        }
    }
}

// ---------------- host ----------------
extern "C" void kernel_launch(void* const* d_in, const int* in_sizes, int n_in,
                              void* d_out, int out_size) {
    const float* act      = (const float*)d_in[0];
    const void*  pm       = d_in[1];
    const float* ln_scale = (const float*)d_in[2];
    const float* ln_bias  = (const float*)d_in[3];
    const float* w_pb     = (const float*)d_in[4];
    const float* w_q      = (const float*)d_in[5];
    const float* w_k      = (const float*)d_in[6];
    const float* w_v      = (const float*)d_in[7];
    const float* w_gate   = (const float*)d_in[8];
    const float* b_gate   = (const float*)d_in[9];
    const float* w_out    = (const float*)d_in[10];
    const float* b_out    = (const float*)d_in[11];
    float* out = (float*)d_out;

    conv_w_kernel<<<dim3(5, 16), 128>>>(w_q, w_k, w_v, w_gate, w_out);
    ln_bias_kernel<<<M_TOT / 8, 256>>>(act, ln_scale, ln_bias, w_pb);

    cudaFuncSetAttribute(proj_mma_kernel, cudaFuncAttributeMaxDynamicSharedMemorySize,
                         MMA_SMEM_BYTES);
    proj_mma_kernel<<<dim3(400, 4), 256, MMA_SMEM_BYTES>>>(b_gate);

    cudaFuncSetAttribute(attn_mma_kernel, cudaFuncAttributeMaxDynamicSharedMemorySize,
                         ATTN_SMEM);
    attn_mma_kernel<<<NRES * NH, 512, ATTN_SMEM>>>(pm);

    cudaFuncSetAttribute(out_mma_kernel, cudaFuncAttributeMaxDynamicSharedMemorySize,
                         MMA_SMEM_BYTES);
    out_mma_kernel<<<400, 256, MMA_SMEM_BYTES>>>(b_out, out);
}

// round 15
// speedup vs baseline: 4.4669x; 1.3840x over previous
#include <cuda_runtime.h>
#include <cuda_fp16.h>
#include <math.h>
#include <stdint.h>

// Problem constants
#define NRES 320
#define CCH  128
#define NH   4
#define DD   32
#define HD   128            // NH*DD
#define M_TOT (NRES*NRES)   // 102400
#define APAD 136            // GEMM smem row stride (fp16 elems), conflict-free
#define QSCALE 0.17677669529663687f  // 1/sqrt(32)

// ---------------- scratch (device globals) ----------------
__device__ __half g_x[M_TOT * CCH];        // layernormed act, fp16
__device__ __half g_wb[5 * CCH * CCH];     // transposed weights [mat][n][k], fp16
__device__ __half g_q[M_TOT * HD];         // [m][f], pre-scaled
__device__ __half g_k[M_TOT * HD];
__device__ __half g_v[M_TOT * HD];
__device__ float  g_gate[M_TOT * HD];
__device__ __half g_wa[M_TOT * HD];        // gated attn out, fp16
__device__ float  g_bias[NH * M_TOT];      // [h][q][k]

__device__ __forceinline__ float warpReduceSum(float v) {
    #pragma unroll
    for (int o = 16; o; o >>= 1) v += __shfl_xor_sync(0xffffffffu, v, o);
    return v;
}
__device__ __forceinline__ unsigned pack_h2(float a, float b) {
    __half2 t = __floats2half2_rn(a, b);
    return *reinterpret_cast<unsigned*>(&t);
}

#define MMA_F16(c, a, b0, b1) \
    asm volatile("mma.sync.aligned.m16n8k16.row.col.f32.f16.f16.f32 " \
        "{%0,%1,%2,%3}, {%4,%5,%6,%7}, {%8,%9}, {%0,%1,%2,%3};" \
        : "+f"((c)[0]), "+f"((c)[1]), "+f"((c)[2]), "+f"((c)[3]) \
        : "r"((a)[0]), "r"((a)[1]), "r"((a)[2]), "r"((a)[3]), "r"(b0), "r"(b1))

// ---------------- kernel 1: LayerNorm + pair-bias + fp16 emit ----------------
__global__ void ln_bias_kernel(const float* __restrict__ act,
                               const float* __restrict__ ln_scale,
                               const float* __restrict__ ln_bias,
                               const float* __restrict__ w_pb) {
    int warp = threadIdx.x >> 5, lane = threadIdx.x & 31;
    int pos = blockIdx.x * 8 + warp;
    if (pos >= M_TOT) return;
    size_t base = (size_t)pos * CCH + lane * 4;
    float4 x = *(const float4*)(act + base);

    float s = warpReduceSum(x.x + x.y + x.z + x.w);
    float mu = s * (1.0f / CCH);
    float dx = x.x - mu, dy = x.y - mu, dz = x.z - mu, dw = x.w - mu;
    float sq = warpReduceSum(dx*dx + dy*dy + dz*dz + dw*dw);
    float rstd = rsqrtf(sq * (1.0f / CCH) + 1e-5f);

    float4 sc = *(const float4*)(ln_scale + lane * 4);
    float4 bi = *(const float4*)(ln_bias + lane * 4);
    float4 y;
    y.x = dx * rstd * sc.x + bi.x;
    y.y = dy * rstd * sc.y + bi.y;
    y.z = dz * rstd * sc.z + bi.z;
    y.w = dw * rstd * sc.w + bi.w;

    uint2 hv;
    hv.x = pack_h2(y.x, y.y);
    hv.y = pack_h2(y.z, y.w);
    *(uint2*)(g_x + base) = hv;

    float4 acc = make_float4(0.f, 0.f, 0.f, 0.f);
    {
        float4 p0 = *(const float4*)(w_pb + (lane*4 + 0) * NH);
        float4 p1 = *(const float4*)(w_pb + (lane*4 + 1) * NH);
        float4 p2 = *(const float4*)(w_pb + (lane*4 + 2) * NH);
        float4 p3 = *(const float4*)(w_pb + (lane*4 + 3) * NH);
        acc.x = y.x*p0.x + y.y*p1.x + y.z*p2.x + y.w*p3.x;
        acc.y = y.x*p0.y + y.y*p1.y + y.z*p2.y + y.w*p3.y;
        acc.z = y.x*p0.z + y.y*p1.z + y.z*p2.z + y.w*p3.z;
        acc.w = y.x*p0.w + y.y*p1.w + y.z*p2.w + y.w*p3.w;
    }
    acc.x = warpReduceSum(acc.x);
    acc.y = warpReduceSum(acc.y);
    acc.z = warpReduceSum(acc.z);
    acc.w = warpReduceSum(acc.w);
    if (lane == 0) {
        g_bias[0 * M_TOT + pos] = acc.x;
        g_bias[1 * M_TOT + pos] = acc.y;
        g_bias[2 * M_TOT + pos] = acc.z;
        g_bias[3 * M_TOT + pos] = acc.w;
    }
}

// ---------------- kernel 1b: weight transpose (fp16) ----------------
__global__ void conv_w_kernel(const float* __restrict__ wq, const float* __restrict__ wk,
                              const float* __restrict__ wv, const float* __restrict__ wg,
                              const float* __restrict__ wo) {
    int mat = blockIdx.x;
    const float* W = (mat == 0) ? wq : (mat == 1) ? wk : (mat == 2) ? wv
                   : (mat == 3) ? wg : wo;
    int n = threadIdx.x;
    int k0 = blockIdx.y * 8;
    size_t dst = (size_t)mat * (CCH * CCH) + (size_t)n * CCH;
    #pragma unroll
    for (int kk = 0; kk < 8; kk++) {
        int k = k0 + kk;
        g_wb[dst + k] = __float2half(W[(size_t)k * CCH + n]);   // B[n][k] = W[k][n]
    }
}

// ---------------- 64x128 fp16 mma tile ----------------
// A [64][APAD] (m,k); B [128][APAD] ([n][k] col-major KxN).
// 8 warps: warp_m = wid&1 (32 rows), warp_n = wid>>1 (32 cols).
__device__ __forceinline__ void mma_tile64(const __half* __restrict__ A,
                                           const __half* __restrict__ B,
                                           int wid, int lane, float c[2][4][4]) {
    int warp_m = wid & 1, warp_n = wid >> 1;
    int g = lane >> 2, t4 = lane & 3;
    #pragma unroll
    for (int ks = 0; ks < 8; ks++) {
        int k0 = ks * 16 + t4 * 2;
        uint32_t a[2][4];
        #pragma unroll
        for (int mf = 0; mf < 2; mf++) {
            const __half* pa = A + (warp_m*32 + mf*16 + g) * APAD;
            a[mf][0] = *(const uint32_t*)(pa + k0);
            a[mf][1] = *(const uint32_t*)(pa + 8*APAD + k0);
            a[mf][2] = *(const uint32_t*)(pa + k0 + 8);
            a[mf][3] = *(const uint32_t*)(pa + 8*APAD + k0 + 8);
        }
        #pragma unroll
        for (int nf = 0; nf < 4; nf++) {
            const __half* pb = B + (warp_n*32 + nf*8 + g) * APAD;
            uint32_t b0 = *(const uint32_t*)(pb + k0);
            uint32_t b1 = *(const uint32_t*)(pb + k0 + 8);
            #pragma unroll
            for (int mf = 0; mf < 2; mf++)
                MMA_F16(c[mf][nf], a[mf], b0, b1);
        }
    }
}

// smem element offsets (fp16)
#define SME_A 0             // 64*136  = 8704 elems
#define SME_B 8704          // 128*136 = 17408 elems
#define SME_TOT 26112
#define MMA_SMEM_BYTES (SME_TOT * 2 + 512)   // 52,736 B -> 3+ blocks/SM

// ---------------- kernel 2: QKV/gate projection (fp16, A prefetch) ----------------
__global__ void __launch_bounds__(256, 3)
proj_mma_kernel(const float* __restrict__ bg) {
    extern __shared__ __half sm[];
    __half* As = sm + SME_A;
    __half* Bs = sm + SME_B;
    float* bgs = (float*)(sm + SME_TOT);

    int t = threadIdx.x, wid = t >> 5, lane = t & 31;
    int mat = blockIdx.y;

    if (t < 128) bgs[t] = bg[t];
    {   // B load: 128 rows
        int row = t >> 1, half = t & 1;
        const uint4* sB = (const uint4*)(g_wb + ((size_t)mat * CCH + row) * CCH + half * 64);
        uint4* dB = (uint4*)(Bs + row * APAD + half * 64);
        #pragma unroll
        for (int c = 0; c < 8; c++) dB[c] = sB[c];
    }

    __half* dst = (mat == 0) ? g_q : (mat == 1) ? g_k : g_v;
    int warp_m = wid & 1, warp_n = wid >> 1;
    int g = lane >> 2, t4 = lane & 3;
    int arow = t >> 2, aseg = t & 3;

    // prefetch A tile 0 (64 rows x 128 cols fp16 = 4 uint4/thread)
    uint4 pA[4];
    {
        int m0 = blockIdx.x * 4 * 64;
        const uint4* aS = (const uint4*)(g_x + (size_t)(m0 + arow) * CCH + aseg * 32);
        #pragma unroll
        for (int c = 0; c < 4; c++) pA[c] = aS[c];
    }

    for (int it = 0; it < 4; it++) {
        __syncthreads();
        int m0 = (blockIdx.x * 4 + it) * 64;
        {
            uint4* dA = (uint4*)(As + arow * APAD + aseg * 32);
            #pragma unroll
            for (int c = 0; c < 4; c++) dA[c] = pA[c];
        }
        __syncthreads();
        if (it < 3) {
            int m1 = (blockIdx.x * 4 + it + 1) * 64;
            const uint4* aS = (const uint4*)(g_x + (size_t)(m1 + arow) * CCH + aseg * 32);
            #pragma unroll
            for (int c = 0; c < 4; c++) pA[c] = aS[c];
        }

        float c[2][4][4];
        #pragma unroll
        for (int mf = 0; mf < 2; mf++)
            #pragma unroll
            for (int nf = 0; nf < 4; nf++)
                #pragma unroll
                for (int j = 0; j < 4; j++) c[mf][nf][j] = 0.f;

        mma_tile64(As, Bs, wid, lane, c);

        #pragma unroll
        for (int mf = 0; mf < 2; mf++) {
            int r = m0 + warp_m * 32 + mf * 16 + g;
            #pragma unroll
            for (int nf = 0; nf < 4; nf++) {
                int cc = warp_n * 32 + nf * 8 + t4 * 2;
                float v0 = c[mf][nf][0], v1 = c[mf][nf][1];
                float v2 = c[mf][nf][2], v3 = c[mf][nf][3];
                if (mat == 3) {
                    float b0 = bgs[cc], b1 = bgs[cc + 1];
                    v0 = 1.0f / (1.0f + __expf(-(v0 + b0)));
                    v1 = 1.0f / (1.0f + __expf(-(v1 + b1)));
                    v2 = 1.0f / (1.0f + __expf(-(v2 + b0)));
                    v3 = 1.0f / (1.0f + __expf(-(v3 + b1)));
                    *(float2*)(g_gate + (size_t)r * HD + cc) = make_float2(v0, v1);
                    *(float2*)(g_gate + (size_t)(r + 8) * HD + cc) = make_float2(v2, v3);
                } else {
                    if (mat == 0) { v0 *= QSCALE; v1 *= QSCALE; v2 *= QSCALE; v3 *= QSCALE; }
                    *(uint32_t*)(dst + (size_t)r * HD + cc) = pack_h2(v0, v1);
                    *(uint32_t*)(dst + (size_t)(r + 8) * HD + cc) = pack_h2(v2, v3);
                }
            }
        }
    }
}

// ---------------- kernel 3: attention, 512 threads, fp16 mma ----------------
// smem (fp16 elem offsets): KH 320x40, VTH 32x328, QH 64x40
#define AT_K   0
#define AT_VT  12800
#define AT_Q   23296
#define AT_FP  25856          // float region at byte 51712
#define KPAD  40
#define VTPAD 328
#define OPAD  33
#define OSZ   (64 * OPAD)     // 2112 floats per partial buffer
#define ATTN_SMEM (51712 + (320 + 256 + 4 * OSZ) * 4)   // 87,808 B

__global__ void __launch_bounds__(512, 1)
attn_mma_kernel(const void* __restrict__ pmv) {
    extern __shared__ __half sb[];
    __half* Ks  = sb + AT_K;
    __half* VTs = sb + AT_VT;
    __half* Qs  = sb + AT_Q;
    float* fp   = (float*)(sb + AT_FP);
    float* Msk  = fp;          // [320]
    float* Sums = fp + 320;    // [4][64]
    float* OsmP = fp + 576;    // [4][64][33]

    int b = blockIdx.x >> 2, h = blockIdx.x & 3;
    int t = threadIdx.x, wid = t >> 5, lane = t & 31;
    int g = lane >> 2, t4 = lane & 3;
    int warp_q = wid & 3, warp_k = wid >> 2;
    size_t mbase = (size_t)b * NRES * HD + (size_t)h * DD;

    for (int i = t; i < 5120; i += 512) {
        int row = i >> 4, c2 = (i & 15) * 2;
        size_t src = mbase + (size_t)row * HD + c2;
        *(uint32_t*)(Ks + row * KPAD + c2) = *(const uint32_t*)(g_k + src);
        uint32_t vh = *(const uint32_t*)(g_v + src);
        __half2 vh2 = *reinterpret_cast<__half2*>(&vh);
        VTs[c2 * VTPAD + row] = vh2.x;
        VTs[(c2 + 1) * VTPAD + row] = vh2.y;
    }
    {
        unsigned w0 = ((const unsigned*)pmv)[0];
        int mode = (w0 == 0x3F800000u) ? 0 : (w0 == 0x01010101u) ? 1 : 2;
        for (int i = t; i < NRES; i += 512) {
            size_t idx = (size_t)i * NRES + b;
            bool mv;
            if (mode == 0)      mv = ((const float*)pmv)[idx] != 0.0f;
            else if (mode == 1) mv = ((const unsigned char*)pmv)[idx] != 0;
            else                mv = ((const int*)pmv)[idx] != 0;
            Msk[i] = mv ? 1.0f : 0.0f;
        }
    }
    __syncthreads();

    for (int qt = 0; qt < 5; qt++) {
        int q0 = qt * 64;
        // Q tile: 64 rows x 16 uint32 = 1024 words (2 passes)
        for (int i = t; i < 1024; i += 512) {
            int row = i >> 4, c2 = (i & 15) * 2;
            size_t src = mbase + (size_t)(q0 + row) * HD + c2;
            *(uint32_t*)(Qs + row * KPAD + c2) = *(const uint32_t*)(g_q + src);
        }
        __syncthreads();   // Q ready; prior-iter epilogue Osm reads done

        // ---- QK^T over this warp's 80-key slice ----
        float c[10][4];
        #pragma unroll
        for (int nf = 0; nf < 10; nf++)
            #pragma unroll
            for (int j = 0; j < 4; j++) c[nf][j] = 0.f;

        uint32_t aQ[2][4];
        #pragma unroll
        for (int ks = 0; ks < 2; ks++) {
            const __half* pa = Qs + (warp_q*16 + g) * KPAD + ks*16 + 2*t4;
            aQ[ks][0] = *(const uint32_t*)pa;
            aQ[ks][1] = *(const uint32_t*)(pa + 8*KPAD);
            aQ[ks][2] = *(const uint32_t*)(pa + 8);
            aQ[ks][3] = *(const uint32_t*)(pa + 8*KPAD + 8);
        }
        #pragma unroll
        for (int nf = 0; nf < 10; nf++) {
            int krow = warp_k*80 + nf*8 + g;
            #pragma unroll
            for (int ks = 0; ks < 2; ks++) {
                const __half* pb = Ks + krow * KPAD + ks*16 + 2*t4;
                uint32_t b0 = *(const uint32_t*)pb;
                uint32_t b1 = *(const uint32_t*)(pb + 8);
                MMA_F16(c[nf], aQ[ks], b0, b1);
            }
        }

        // ---- bias + mask + exp + partial row sums ----
        int qr = q0 + warp_q*16 + g;
        const float* bp = g_bias + (size_t)h * M_TOT;
        float s0 = 0.f, s1 = 0.f;
        #pragma unroll
        for (int nf = 0; nf < 10; nf++) {
            int k = warp_k*80 + nf*8 + 2*t4;
            float2 b0 = *(const float2*)(bp + (size_t)qr * NRES + k);
            float2 b1 = *(const float2*)(bp + (size_t)(qr + 8) * NRES + k);
            float m0 = Msk[k], m1 = Msk[k + 1];
            // clamp at 11 so exp result stays within fp16 range for the P pack
            c[nf][0] = __expf(fminf(c[nf][0] + b0.x, 11.f)) * m0;
            c[nf][1] = __expf(fminf(c[nf][1] + b0.y, 11.f)) * m1;
            c[nf][2] = __expf(fminf(c[nf][2] + b1.x, 11.f)) * m0;
            c[nf][3] = __expf(fminf(c[nf][3] + b1.y, 11.f)) * m1;
            s0 += c[nf][0] + c[nf][1];
            s1 += c[nf][2] + c[nf][3];
        }
        s0 += __shfl_xor_sync(0xffffffffu, s0, 1);
        s0 += __shfl_xor_sync(0xffffffffu, s0, 2);
        s1 += __shfl_xor_sync(0xffffffffu, s1, 1);
        s1 += __shfl_xor_sync(0xffffffffu, s1, 2);
        if (t4 == 0) {
            Sums[warp_k*64 + warp_q*16 + g]     = s0;
            Sums[warp_k*64 + warp_q*16 + g + 8] = s1;
        }

        // ---- P (fp16) @ V (fp16) over 80 keys ----
        float o[4][4];
        #pragma unroll
        for (int nf = 0; nf < 4; nf++)
            #pragma unroll
            for (int j = 0; j < 4; j++) o[nf][j] = 0.f;

        #pragma unroll
        for (int ks = 0; ks < 5; ks++) {
            uint32_t aP[4];
            aP[0] = pack_h2(c[2*ks][0],   c[2*ks][1]);
            aP[1] = pack_h2(c[2*ks][2],   c[2*ks][3]);
            aP[2] = pack_h2(c[2*ks+1][0], c[2*ks+1][1]);
            aP[3] = pack_h2(c[2*ks+1][2], c[2*ks+1][3]);
            int k0 = warp_k*80 + ks*16 + 2*t4;
            #pragma unroll
            for (int nf = 0; nf < 4; nf++) {
                const __half* pb = VTs + (nf*8 + g) * VTPAD + k0;
                uint32_t b0 = *(const uint32_t*)pb;
                uint32_t b1 = *(const uint32_t*)(pb + 8);
                MMA_F16(o[nf], aP, b0, b1);
            }
        }

        // ---- each warp_k group writes its own partial buffer ----
        {
            float* myO = OsmP + warp_k * OSZ;
            int r0 = warp_q*16 + g;
            #pragma unroll
            for (int nf = 0; nf < 4; nf++) {
                int cc = nf*8 + 2*t4;
                myO[r0*OPAD + cc]         = o[nf][0];
                myO[r0*OPAD + cc + 1]     = o[nf][1];
                myO[(r0+8)*OPAD + cc]     = o[nf][2];
                myO[(r0+8)*OPAD + cc + 1] = o[nf][3];
            }
        }
        __syncthreads();

        // ---- epilogue: sum partials, normalize, gate, fp16 store ----
        {
            int row = t >> 3, cb = (t & 7) * 4;
            float den = Sums[row] + Sums[64 + row] + Sums[128 + row] + Sums[192 + row];
            float inv = (den > 0.f) ? 1.0f / den : 0.f;
            int ob = row * OPAD + cb;
            float v0 = OsmP[ob+0] + OsmP[OSZ+ob+0] + OsmP[2*OSZ+ob+0] + OsmP[3*OSZ+ob+0];
            float v1 = OsmP[ob+1] + OsmP[OSZ+ob+1] + OsmP[2*OSZ+ob+1] + OsmP[3*OSZ+ob+1];
            float v2 = OsmP[ob+2] + OsmP[OSZ+ob+2] + OsmP[2*OSZ+ob+2] + OsmP[3*OSZ+ob+2];
            float v3 = OsmP[ob+3] + OsmP[OSZ+ob+3] + OsmP[2*OSZ+ob+3] + OsmP[3*OSZ+ob+3];
            size_t m = (size_t)b * NRES + q0 + row;
            float4 gv = *(const float4*)(g_gate + m * HD + h * DD + cb);
            v0 *= inv * gv.x; v1 *= inv * gv.y; v2 *= inv * gv.z; v3 *= inv * gv.w;
            size_t doff = m * HD + h * DD + cb;
            *(uint32_t*)(g_wa + doff)     = pack_h2(v0, v1);
            *(uint32_t*)(g_wa + doff + 2) = pack_h2(v2, v3);
        }
    }
}

// ---------------- kernel 4: output projection (fp16, A prefetch) ----------------
__global__ void __launch_bounds__(256, 3)
out_mma_kernel(const float* __restrict__ bo, float* __restrict__ out) {
    extern __shared__ __half sm[];
    __half* As = sm + SME_A;
    __half* Bs = sm + SME_B;
    float* bos = (float*)(sm + SME_TOT);

    int t = threadIdx.x, wid = t >> 5, lane = t & 31;
    if (t < 128) bos[t] = bo[t];
    {
        int row = t >> 1, half = t & 1;
        const uint4* sB = (const uint4*)(g_wb + ((size_t)4 * CCH + row) * CCH + half * 64);
        uint4* dB = (uint4*)(Bs + row * APAD + half * 64);
        #pragma unroll
        for (int c = 0; c < 8; c++) dB[c] = sB[c];
    }

    int warp_m = wid & 1, warp_n = wid >> 1;
    int g = lane >> 2, t4 = lane & 3;
    int arow = t >> 2, aseg = t & 3;

    uint4 pA[4];
    {
        int m0 = blockIdx.x * 4 * 64;
        const uint4* aS = (const uint4*)(g_wa + (size_t)(m0 + arow) * HD + aseg * 32);
        #pragma unroll
        for (int c = 0; c < 4; c++) pA[c] = aS[c];
    }

    for (int it = 0; it < 4; it++) {
        __syncthreads();
        int m0 = (blockIdx.x * 4 + it) * 64;
        {
            uint4* dA = (uint4*)(As + arow * APAD + aseg * 32);
            #pragma unroll
            for (int c = 0; c < 4; c++) dA[c] = pA[c];
        }
        __syncthreads();
        if (it < 3) {
            int m1 = (blockIdx.x * 4 + it + 1) * 64;
            const uint4* aS = (const uint4*)(g_wa + (size_t)(m1 + arow) * HD + aseg * 32);
            #pragma unroll
            for (int c = 0; c < 4; c++) pA[c] = aS[c];
        }

        float c[2][4][4];
        #pragma unroll
        for (int mf = 0; mf < 2; mf++)
            #pragma unroll
            for (int nf = 0; nf < 4; nf++)
                #pragma unroll
                for (int j = 0; j < 4; j++) c[mf][nf][j] = 0.f;

        mma_tile64(As, Bs, wid, lane, c);

        #pragma unroll
        for (int mf = 0; mf < 2; mf++) {
            int r = m0 + warp_m * 32 + mf * 16 + g;
            #pragma unroll
            for (int nf = 0; nf < 4; nf++) {
                int cc = warp_n * 32 + nf * 8 + t4 * 2;
                float b0 = bos[cc], b1 = bos[cc + 1];
                *(float2*)(out + (size_t)r * CCH + cc) =
                    make_float2(c[mf][nf][0] + b0, c[mf][nf][1] + b1);
                *(float2*)(out + (size_t)(r + 8) * CCH + cc) =
                    make_float2(c[mf][nf][2] + b0, c[mf][nf][3] + b1);
            }
        }
    }
}

// ---------------- host ----------------
extern "C" void kernel_launch(void* const* d_in, const int* in_sizes, int n_in,
                              void* d_out, int out_size) {
    const float* act      = (const float*)d_in[0];
    const void*  pm       = d_in[1];
    const float* ln_scale = (const float*)d_in[2];
    const float* ln_bias  = (const float*)d_in[3];
    const float* w_pb     = (const float*)d_in[4];
    const float* w_q      = (const float*)d_in[5];
    const float* w_k      = (const float*)d_in[6];
    const float* w_v      = (const float*)d_in[7];
    const float* w_gate   = (const float*)d_in[8];
    const float* b_gate   = (const float*)d_in[9];
    const float* w_out    = (const float*)d_in[10];
    const float* b_out    = (const float*)d_in[11];
    float* out = (float*)d_out;

    conv_w_kernel<<<dim3(5, 16), 128>>>(w_q, w_k, w_v, w_gate, w_out);
    ln_bias_kernel<<<M_TOT / 8, 256>>>(act, ln_scale, ln_bias, w_pb);

    cudaFuncSetAttribute(proj_mma_kernel, cudaFuncAttributeMaxDynamicSharedMemorySize,
                         MMA_SMEM_BYTES);
    proj_mma_kernel<<<dim3(400, 4), 256, MMA_SMEM_BYTES>>>(b_gate);

    cudaFuncSetAttribute(attn_mma_kernel, cudaFuncAttributeMaxDynamicSharedMemorySize,
                         ATTN_SMEM);
    attn_mma_kernel<<<NRES * NH, 512, ATTN_SMEM>>>(pm);

    cudaFuncSetAttribute(out_mma_kernel, cudaFuncAttributeMaxDynamicSharedMemorySize,
                         MMA_SMEM_BYTES);
    out_mma_kernel<<<400, 256, MMA_SMEM_BYTES>>>(b_out, out);
}

// round 17
// speedup vs baseline: 6.1099x; 1.3678x over previous
#include <cuda_runtime.h>
#include <cuda_fp16.h>
#include <math.h>
#include <stdint.h>

// Problem constants
#define NRES 320
#define CCH  128
#define NH   4
#define DD   32
#define HD   128            // NH*DD
#define M_TOT (NRES*NRES)   // 102400
#define APAD 136            // GEMM smem row stride (fp16 elems), conflict-free
#define QSCALE 0.17677669529663687f  // 1/sqrt(32)

// ---------------- scratch (device globals) ----------------
__device__ __half g_x[M_TOT * CCH];        // layernormed act, fp16
__device__ __half g_wb[5 * CCH * CCH];     // transposed weights [mat][n][k], fp16
__device__ __half g_q[M_TOT * HD];         // [m][f], pre-scaled
__device__ __half g_k[M_TOT * HD];
__device__ __half g_v[M_TOT * HD];
__device__ float  g_gate[M_TOT * HD];
__device__ __half g_wa[M_TOT * HD];        // gated attn out, fp16
__device__ float  g_bias[NH * M_TOT];      // [h][q][k]

__device__ __forceinline__ float warpReduceSum(float v) {
    #pragma unroll
    for (int o = 16; o; o >>= 1) v += __shfl_xor_sync(0xffffffffu, v, o);
    return v;
}
__device__ __forceinline__ unsigned pack_h2(float a, float b) {
    __half2 t = __floats2half2_rn(a, b);
    return *reinterpret_cast<unsigned*>(&t);
}

#define MMA_F16(c, a, b0, b1) \
    asm volatile("mma.sync.aligned.m16n8k16.row.col.f32.f16.f16.f32 " \
        "{%0,%1,%2,%3}, {%4,%5,%6,%7}, {%8,%9}, {%0,%1,%2,%3};" \
        : "+f"((c)[0]), "+f"((c)[1]), "+f"((c)[2]), "+f"((c)[3]) \
        : "r"((a)[0]), "r"((a)[1]), "r"((a)[2]), "r"((a)[3]), "r"(b0), "r"(b1))

// ---------------- kernel 1: LayerNorm + pair-bias + fp16 emit ----------------
__global__ void ln_bias_kernel(const float* __restrict__ act,
                               const float* __restrict__ ln_scale,
                               const float* __restrict__ ln_bias,
                               const float* __restrict__ w_pb) {
    int warp = threadIdx.x >> 5, lane = threadIdx.x & 31;
    int pos = blockIdx.x * 8 + warp;
    if (pos >= M_TOT) return;
    size_t base = (size_t)pos * CCH + lane * 4;
    float4 x = *(const float4*)(act + base);

    float s = warpReduceSum(x.x + x.y + x.z + x.w);
    float mu = s * (1.0f / CCH);
    float dx = x.x - mu, dy = x.y - mu, dz = x.z - mu, dw = x.w - mu;
    float sq = warpReduceSum(dx*dx + dy*dy + dz*dz + dw*dw);
    float rstd = rsqrtf(sq * (1.0f / CCH) + 1e-5f);

    float4 sc = *(const float4*)(ln_scale + lane * 4);
    float4 bi = *(const float4*)(ln_bias + lane * 4);
    float4 y;
    y.x = dx * rstd * sc.x + bi.x;
    y.y = dy * rstd * sc.y + bi.y;
    y.z = dz * rstd * sc.z + bi.z;
    y.w = dw * rstd * sc.w + bi.w;

    uint2 hv;
    hv.x = pack_h2(y.x, y.y);
    hv.y = pack_h2(y.z, y.w);
    *(uint2*)(g_x + base) = hv;

    float4 acc = make_float4(0.f, 0.f, 0.f, 0.f);
    {
        float4 p0 = *(const float4*)(w_pb + (lane*4 + 0) * NH);
        float4 p1 = *(const float4*)(w_pb + (lane*4 + 1) * NH);
        float4 p2 = *(const float4*)(w_pb + (lane*4 + 2) * NH);
        float4 p3 = *(const float4*)(w_pb + (lane*4 + 3) * NH);
        acc.x = y.x*p0.x + y.y*p1.x + y.z*p2.x + y.w*p3.x;
        acc.y = y.x*p0.y + y.y*p1.y + y.z*p2.y + y.w*p3.y;
        acc.z = y.x*p0.z + y.y*p1.z + y.z*p2.z + y.w*p3.z;
        acc.w = y.x*p0.w + y.y*p1.w + y.z*p2.w + y.w*p3.w;
    }
    acc.x = warpReduceSum(acc.x);
    acc.y = warpReduceSum(acc.y);
    acc.z = warpReduceSum(acc.z);
    acc.w = warpReduceSum(acc.w);
    if (lane == 0) {
        g_bias[0 * M_TOT + pos] = acc.x;
        g_bias[1 * M_TOT + pos] = acc.y;
        g_bias[2 * M_TOT + pos] = acc.z;
        g_bias[3 * M_TOT + pos] = acc.w;
    }
}

// ---------------- kernel 1b: weight transpose (fp16) ----------------
__global__ void conv_w_kernel(const float* __restrict__ wq, const float* __restrict__ wk,
                              const float* __restrict__ wv, const float* __restrict__ wg,
                              const float* __restrict__ wo) {
    int mat = blockIdx.x;
    const float* W = (mat == 0) ? wq : (mat == 1) ? wk : (mat == 2) ? wv
                   : (mat == 3) ? wg : wo;
    int n = threadIdx.x;
    int k0 = blockIdx.y * 8;
    size_t dst = (size_t)mat * (CCH * CCH) + (size_t)n * CCH;
    #pragma unroll
    for (int kk = 0; kk < 8; kk++) {
        int k = k0 + kk;
        g_wb[dst + k] = __float2half(W[(size_t)k * CCH + n]);   // B[n][k] = W[k][n]
    }
}

// ---------------- 64x128 fp16 mma tile ----------------
__device__ __forceinline__ void mma_tile64(const __half* __restrict__ A,
                                           const __half* __restrict__ B,
                                           int wid, int lane, float c[2][4][4]) {
    int warp_m = wid & 1, warp_n = wid >> 1;
    int g = lane >> 2, t4 = lane & 3;
    #pragma unroll
    for (int ks = 0; ks < 8; ks++) {
        int k0 = ks * 16 + t4 * 2;
        uint32_t a[2][4];
        #pragma unroll
        for (int mf = 0; mf < 2; mf++) {
            const __half* pa = A + (warp_m*32 + mf*16 + g) * APAD;
            a[mf][0] = *(const uint32_t*)(pa + k0);
            a[mf][1] = *(const uint32_t*)(pa + 8*APAD + k0);
            a[mf][2] = *(const uint32_t*)(pa + k0 + 8);
            a[mf][3] = *(const uint32_t*)(pa + 8*APAD + k0 + 8);
        }
        #pragma unroll
        for (int nf = 0; nf < 4; nf++) {
            const __half* pb = B + (warp_n*32 + nf*8 + g) * APAD;
            uint32_t b0 = *(const uint32_t*)(pb + k0);
            uint32_t b1 = *(const uint32_t*)(pb + k0 + 8);
            #pragma unroll
            for (int mf = 0; mf < 2; mf++)
                MMA_F16(c[mf][nf], a[mf], b0, b1);
        }
    }
}

// smem element offsets (fp16)
#define SME_A 0
#define SME_B 8704
#define SME_TOT 26112
#define MMA_SMEM_BYTES (SME_TOT * 2 + 512)   // 52,736 B

// ---------------- kernel 2: QKV/gate projection (fp16, A prefetch) ----------------
__global__ void __launch_bounds__(256, 3)
proj_mma_kernel(const float* __restrict__ bg) {
    extern __shared__ __half sm[];
    __half* As = sm + SME_A;
    __half* Bs = sm + SME_B;
    float* bgs = (float*)(sm + SME_TOT);

    int t = threadIdx.x, wid = t >> 5, lane = t & 31;
    int mat = blockIdx.y;

    if (t < 128) bgs[t] = bg[t];
    {
        int row = t >> 1, half = t & 1;
        const uint4* sB = (const uint4*)(g_wb + ((size_t)mat * CCH + row) * CCH + half * 64);
        uint4* dB = (uint4*)(Bs + row * APAD + half * 64);
        #pragma unroll
        for (int c = 0; c < 8; c++) dB[c] = sB[c];
    }

    __half* dst = (mat == 0) ? g_q : (mat == 1) ? g_k : g_v;
    int warp_m = wid & 1, warp_n = wid >> 1;
    int g = lane >> 2, t4 = lane & 3;
    int arow = t >> 2, aseg = t & 3;

    uint4 pA[4];
    {
        int m0 = blockIdx.x * 4 * 64;
        const uint4* aS = (const uint4*)(g_x + (size_t)(m0 + arow) * CCH + aseg * 32);
        #pragma unroll
        for (int c = 0; c < 4; c++) pA[c] = aS[c];
    }

    for (int it = 0; it < 4; it++) {
        __syncthreads();
        int m0 = (blockIdx.x * 4 + it) * 64;
        {
            uint4* dA = (uint4*)(As + arow * APAD + aseg * 32);
            #pragma unroll
            for (int c = 0; c < 4; c++) dA[c] = pA[c];
        }
        __syncthreads();
        if (it < 3) {
            int m1 = (blockIdx.x * 4 + it + 1) * 64;
            const uint4* aS = (const uint4*)(g_x + (size_t)(m1 + arow) * CCH + aseg * 32);
            #pragma unroll
            for (int c = 0; c < 4; c++) pA[c] = aS[c];
        }

        float c[2][4][4];
        #pragma unroll
        for (int mf = 0; mf < 2; mf++)
            #pragma unroll
            for (int nf = 0; nf < 4; nf++)
                #pragma unroll
                for (int j = 0; j < 4; j++) c[mf][nf][j] = 0.f;

        mma_tile64(As, Bs, wid, lane, c);

        #pragma unroll
        for (int mf = 0; mf < 2; mf++) {
            int r = m0 + warp_m * 32 + mf * 16 + g;
            #pragma unroll
            for (int nf = 0; nf < 4; nf++) {
                int cc = warp_n * 32 + nf * 8 + t4 * 2;
                float v0 = c[mf][nf][0], v1 = c[mf][nf][1];
                float v2 = c[mf][nf][2], v3 = c[mf][nf][3];
                if (mat == 3) {
                    float b0 = bgs[cc], b1 = bgs[cc + 1];
                    v0 = 1.0f / (1.0f + __expf(-(v0 + b0)));
                    v1 = 1.0f / (1.0f + __expf(-(v1 + b1)));
                    v2 = 1.0f / (1.0f + __expf(-(v2 + b0)));
                    v3 = 1.0f / (1.0f + __expf(-(v3 + b1)));
                    *(float2*)(g_gate + (size_t)r * HD + cc) = make_float2(v0, v1);
                    *(float2*)(g_gate + (size_t)(r + 8) * HD + cc) = make_float2(v2, v3);
                } else {
                    if (mat == 0) { v0 *= QSCALE; v1 *= QSCALE; v2 *= QSCALE; v3 *= QSCALE; }
                    *(uint32_t*)(dst + (size_t)r * HD + cc) = pack_h2(v0, v1);
                    *(uint32_t*)(dst + (size_t)(r + 8) * HD + cc) = pack_h2(v2, v3);
                }
            }
        }
    }
}

// ---------------- kernel 3: attention — barrier-free, warp owns 16q x 320k ----------------
// smem (fp16 elems): K 320x40 @0, VT 32x328 @12800, mask floats @23296
#define KPAD  40
#define VTPAD 328
#define AT_VT  12800
#define AT_MSK 23296
#define ATTN_SMEM (23296 * 2 + 320 * 4)   // 47,872 B -> 2 blocks/SM

__global__ void __launch_bounds__(320, 2)
attn_mma_kernel(const void* __restrict__ pmv) {
    extern __shared__ __half sb[];
    __half* Ks  = sb;
    __half* VTs = sb + AT_VT;
    float* Msk  = (float*)(sb + AT_MSK);

    int b = blockIdx.x >> 2, h = blockIdx.x & 3;
    int t = threadIdx.x, wid = t >> 5, lane = t & 31;
    int g = lane >> 2, t4 = lane & 3;
    size_t mbase = (size_t)b * NRES * HD + (size_t)h * DD;

    // load K and V-transposed
    for (int i = t; i < 5120; i += 320) {
        int row = i >> 4, c2 = (i & 15) * 2;
        size_t src = mbase + (size_t)row * HD + c2;
        *(uint32_t*)(Ks + row * KPAD + c2) = *(const uint32_t*)(g_k + src);
        uint32_t vh = *(const uint32_t*)(g_v + src);
        __half2 vh2 = *reinterpret_cast<__half2*>(&vh);
        VTs[c2 * VTPAD + row] = vh2.x;
        VTs[(c2 + 1) * VTPAD + row] = vh2.y;
    }
    {
        unsigned w0 = ((const unsigned*)pmv)[0];
        int mode = (w0 == 0x3F800000u) ? 0 : (w0 == 0x01010101u) ? 1 : 2;
        for (int i = t; i < NRES; i += 320) {
            size_t idx = (size_t)i * NRES + b;
            bool mv;
            if (mode == 0)      mv = ((const float*)pmv)[idx] != 0.0f;
            else if (mode == 1) mv = ((const unsigned char*)pmv)[idx] != 0;
            else                mv = ((const int*)pmv)[idx] != 0;
            Msk[i] = mv ? 1.0f : 0.0f;
        }
    }
    __syncthreads();   // the ONLY block-wide barrier

    #pragma unroll
    for (int pass = 0; pass < 2; pass++) {
        int qbase = pass * 160 + wid * 16;

        // Q fragments straight from global
        uint32_t aQ[2][4];
        {
            const __half* qp = g_q + mbase + (size_t)(qbase + g) * HD;
            #pragma unroll
            for (int ks = 0; ks < 2; ks++) {
                int co = ks * 16 + 2 * t4;
                aQ[ks][0] = *(const uint32_t*)(qp + co);
                aQ[ks][1] = *(const uint32_t*)(qp + 8 * HD + co);
                aQ[ks][2] = *(const uint32_t*)(qp + co + 8);
                aQ[ks][3] = *(const uint32_t*)(qp + 8 * HD + co + 8);
            }
        }

        float o[4][4];
        #pragma unroll
        for (int nf = 0; nf < 4; nf++)
            #pragma unroll
            for (int j = 0; j < 4; j++) o[nf][j] = 0.f;
        float s0 = 0.f, s1 = 0.f;

        const float* bp0 = g_bias + (size_t)h * M_TOT + (size_t)(qbase + g) * NRES;
        const float* bp1 = bp0 + 8 * NRES;

        #pragma unroll
        for (int ch = 0; ch < 4; ch++) {
            int kbase = ch * 80;

            // ---- QK^T chunk: 16 q-rows x 80 keys ----
            float c[10][4];
            #pragma unroll
            for (int nf = 0; nf < 10; nf++)
                #pragma unroll
                for (int j = 0; j < 4; j++) c[nf][j] = 0.f;

            #pragma unroll
            for (int nf = 0; nf < 10; nf++) {
                int krow = kbase + nf * 8 + g;
                #pragma unroll
                for (int ks = 0; ks < 2; ks++) {
                    const __half* pb = Ks + krow * KPAD + ks * 16 + 2 * t4;
                    uint32_t b0 = *(const uint32_t*)pb;
                    uint32_t b1 = *(const uint32_t*)(pb + 8);
                    MMA_F16(c[nf], aQ[ks], b0, b1);
                }
            }

            // ---- bias + mask + exp + sum accumulate ----
            #pragma unroll
            for (int nf = 0; nf < 10; nf++) {
                int k = kbase + nf * 8 + 2 * t4;
                float2 b0 = *(const float2*)(bp0 + k);
                float2 b1 = *(const float2*)(bp1 + k);
                float m0 = Msk[k], m1 = Msk[k + 1];
                c[nf][0] = __expf(fminf(c[nf][0] + b0.x, 11.f)) * m0;
                c[nf][1] = __expf(fminf(c[nf][1] + b0.y, 11.f)) * m1;
                c[nf][2] = __expf(fminf(c[nf][2] + b1.x, 11.f)) * m0;
                c[nf][3] = __expf(fminf(c[nf][3] + b1.y, 11.f)) * m1;
                s0 += c[nf][0] + c[nf][1];
                s1 += c[nf][2] + c[nf][3];
            }

            // ---- P (fp16) @ V chunk, accumulate into o ----
            #pragma unroll
            for (int ks = 0; ks < 5; ks++) {
                uint32_t aP[4];
                aP[0] = pack_h2(c[2*ks][0],   c[2*ks][1]);
                aP[1] = pack_h2(c[2*ks][2],   c[2*ks][3]);
                aP[2] = pack_h2(c[2*ks+1][0], c[2*ks+1][1]);
                aP[3] = pack_h2(c[2*ks+1][2], c[2*ks+1][3]);
                int k0 = kbase + ks * 16 + 2 * t4;
                #pragma unroll
                for (int nf = 0; nf < 4; nf++) {
                    const __half* pb = VTs + (nf * 8 + g) * VTPAD + k0;
                    uint32_t b0 = *(const uint32_t*)pb;
                    uint32_t b1 = *(const uint32_t*)(pb + 8);
                    MMA_F16(o[nf], aP, b0, b1);
                }
            }
        }

        // ---- in-warp row-sum completion (lanes sharing a row: t4 group) ----
        s0 += __shfl_xor_sync(0xffffffffu, s0, 1);
        s0 += __shfl_xor_sync(0xffffffffu, s0, 2);
        s1 += __shfl_xor_sync(0xffffffffu, s1, 1);
        s1 += __shfl_xor_sync(0xffffffffu, s1, 2);
        float inv0 = (s0 > 0.f) ? 1.0f / s0 : 0.f;
        float inv1 = (s1 > 0.f) ? 1.0f / s1 : 0.f;

        // ---- epilogue: normalize, gate, fp16 store (no barrier) ----
        {
            int r0 = qbase + g, r1 = qbase + 8 + g;
            size_t d0 = ((size_t)b * NRES + r0) * HD + (size_t)h * DD;
            size_t d1 = ((size_t)b * NRES + r1) * HD + (size_t)h * DD;
            #pragma unroll
            for (int nf = 0; nf < 4; nf++) {
                int cc = nf * 8 + 2 * t4;
                float2 gv0 = *(const float2*)(g_gate + d0 + cc);
                float2 gv1 = *(const float2*)(g_gate + d1 + cc);
                *(uint32_t*)(g_wa + d0 + cc) =
                    pack_h2(o[nf][0] * inv0 * gv0.x, o[nf][1] * inv0 * gv0.y);
                *(uint32_t*)(g_wa + d1 + cc) =
                    pack_h2(o[nf][2] * inv1 * gv1.x, o[nf][3] * inv1 * gv1.y);
            }
        }
    }
}

// ---------------- kernel 4: output projection (fp16, A prefetch) ----------------
__global__ void __launch_bounds__(256, 3)
out_mma_kernel(const float* __restrict__ bo, float* __restrict__ out) {
    extern __shared__ __half sm[];
    __half* As = sm + SME_A;
    __half* Bs = sm + SME_B;
    float* bos = (float*)(sm + SME_TOT);

    int t = threadIdx.x, wid = t >> 5, lane = t & 31;
    if (t < 128) bos[t] = bo[t];
    {
        int row = t >> 1, half = t & 1;
        const uint4* sB = (const uint4*)(g_wb + ((size_t)4 * CCH + row) * CCH + half * 64);
        uint4* dB = (uint4*)(Bs + row * APAD + half * 64);
        #pragma unroll
        for (int c = 0; c < 8; c++) dB[c] = sB[c];
    }

    int warp_m = wid & 1, warp_n = wid >> 1;
    int g = lane >> 2, t4 = lane & 3;
    int arow = t >> 2, aseg = t & 3;

    uint4 pA[4];
    {
        int m0 = blockIdx.x * 4 * 64;
        const uint4* aS = (const uint4*)(g_wa + (size_t)(m0 + arow) * HD + aseg * 32);
        #pragma unroll
        for (int c = 0; c < 4; c++) pA[c] = aS[c];
    }

    for (int it = 0; it < 4; it++) {
        __syncthreads();
        int m0 = (blockIdx.x * 4 + it) * 64;
        {
            uint4* dA = (uint4*)(As + arow * APAD + aseg * 32);
            #pragma unroll
            for (int c = 0; c < 4; c++) dA[c] = pA[c];
        }
        __syncthreads();
        if (it < 3) {
            int m1 = (blockIdx.x * 4 + it + 1) * 64;
            const uint4* aS = (const uint4*)(g_wa + (size_t)(m1 + arow) * HD + aseg * 32);
            #pragma unroll
            for (int c = 0; c < 4; c++) pA[c] = aS[c];
        }

        float c[2][4][4];
        #pragma unroll
        for (int mf = 0; mf < 2; mf++)
            #pragma unroll
            for (int nf = 0; nf < 4; nf++)
                #pragma unroll
                for (int j = 0; j < 4; j++) c[mf][nf][j] = 0.f;

        mma_tile64(As, Bs, wid, lane, c);

        #pragma unroll
        for (int mf = 0; mf < 2; mf++) {
            int r = m0 + warp_m * 32 + mf * 16 + g;
            #pragma unroll
            for (int nf = 0; nf < 4; nf++) {
                int cc = warp_n * 32 + nf * 8 + t4 * 2;
                float b0 = bos[cc], b1 = bos[cc + 1];
                *(float2*)(out + (size_t)r * CCH + cc) =
                    make_float2(c[mf][nf][0] + b0, c[mf][nf][1] + b1);
                *(float2*)(out + (size_t)(r + 8) * CCH + cc) =
                    make_float2(c[mf][nf][2] + b0, c[mf][nf][3] + b1);
            }
        }
    }
}

// ---------------- host ----------------
extern "C" void kernel_launch(void* const* d_in, const int* in_sizes, int n_in,
                              void* d_out, int out_size) {
    const float* act      = (const float*)d_in[0];
    const void*  pm       = d_in[1];
    const float* ln_scale = (const float*)d_in[2];
    const float* ln_bias  = (const float*)d_in[3];
    const float* w_pb     = (const float*)d_in[4];
    const float* w_q      = (const float*)d_in[5];
    const float* w_k      = (const float*)d_in[6];
    const float* w_v      = (const float*)d_in[7];
    const float* w_gate   = (const float*)d_in[8];
    const float* b_gate   = (const float*)d_in[9];
    const float* w_out    = (const float*)d_in[10];
    const float* b_out    = (const float*)d_in[11];
    float* out = (float*)d_out;

    conv_w_kernel<<<dim3(5, 16), 128>>>(w_q, w_k, w_v, w_gate, w_out);
    ln_bias_kernel<<<M_TOT / 8, 256>>>(act, ln_scale, ln_bias, w_pb);

    cudaFuncSetAttribute(proj_mma_kernel, cudaFuncAttributeMaxDynamicSharedMemorySize,
                         MMA_SMEM_BYTES);
    proj_mma_kernel<<<dim3(400, 4), 256, MMA_SMEM_BYTES>>>(b_gate);

    cudaFuncSetAttribute(attn_mma_kernel, cudaFuncAttributeMaxDynamicSharedMemorySize,
                         ATTN_SMEM);
    attn_mma_kernel<<<NRES * NH, 320, ATTN_SMEM>>>(pm);

    cudaFuncSetAttribute(out_mma_kernel, cudaFuncAttributeMaxDynamicSharedMemorySize,
                         MMA_SMEM_BYTES);
    out_mma_kernel<<<400, 256, MMA_SMEM_BYTES>>>(b_out, out);
}